// round 2
// baseline (speedup 1.0000x reference)
#include <cuda_runtime.h>
#include <math.h>

// ---------------- problem constants (fixed by reference) ----------------
#define NB    32
#define HH    32
#define WW    32
#define SEQ   1024          // H*W
#define DIMC  384
#define DIC   768           // 2*DIM
#define MLPD  1536          // 4*DIM
#define TOK   (NB*SEQ)      // 32768 tokens

// ---------------- scratch (device globals; no runtime alloc) ------------
__device__ float g_xn [(size_t)TOK*DIMC];
__device__ float g_xs [(size_t)TOK*DIMC];
__device__ float g_hg1[(size_t)TOK*2*DIC];
__device__ float g_hg2[(size_t)TOK*2*DIC];
__device__ float g_e1 [(size_t)TOK*DIC];
__device__ float g_e2 [(size_t)TOK*DIC];
__device__ float g_y  [(size_t)TOK*DIMC];
__device__ float g_yn [(size_t)TOK*DIMC];
__device__ float g_yh [(size_t)TOK*MLPD];

// ---------------- layer norm: one warp per token row ---------------------
__global__ __launch_bounds__(256) void ln_kernel(
    const float* __restrict__ x, const float* __restrict__ gamma,
    const float* __restrict__ beta, float* __restrict__ out, int rows)
{
    int gw   = (blockIdx.x * blockDim.x + threadIdx.x) >> 5;
    int lane = threadIdx.x & 31;
    if (gw >= rows) return;
    const float* xr = x + (size_t)gw * DIMC;
    float s = 0.f, s2 = 0.f;
    #pragma unroll
    for (int i = lane; i < DIMC; i += 32) { float v = xr[i]; s += v; s2 += v*v; }
    #pragma unroll
    for (int o = 16; o; o >>= 1) {
        s  += __shfl_xor_sync(0xffffffffu, s,  o);
        s2 += __shfl_xor_sync(0xffffffffu, s2, o);
    }
    float mu  = s * (1.f/DIMC);
    float var = s2 * (1.f/DIMC) - mu*mu;
    float inv = rsqrtf(var + 1e-5f);
    float* orow = out + (size_t)gw * DIMC;
    #pragma unroll
    for (int i = lane; i < DIMC; i += 32)
        orow[i] = (xr[i] - mu) * inv * gamma[i] + beta[i];
}

// ---------------- depthwise 3x3 conv, NHWC, pad=1 ------------------------
__global__ __launch_bounds__(256) void dwconv_kernel(
    const float* __restrict__ xn, const float* __restrict__ w,
    const float* __restrict__ b, float* __restrict__ xs)
{
    int idx = blockIdx.x * blockDim.x + threadIdx.x;       // 0 .. TOK*DIMC-1
    if (idx >= TOK*DIMC) return;
    int c = idx % DIMC;
    int p = idx / DIMC;
    int xq = p % WW;
    int yq = (p / WW) % HH;
    int n  = p / SEQ;
    float acc = b[c];
    const float* wc = w + c * 9;
    #pragma unroll
    for (int ky = 0; ky < 3; ky++) {
        int yy = yq + ky - 1;
        if (yy < 0 || yy >= HH) continue;
        #pragma unroll
        for (int kx = 0; kx < 3; kx++) {
            int xx = xq + kx - 1;
            if (xx < 0 || xx >= WW) continue;
            acc += wc[ky*3+kx] * xn[((size_t)n*SEQ + yy*WW + xx)*DIMC + c];
        }
    }
    xs[idx] = acc;
}

// ---------------- SGEMM 128x64x16, 256 thr, 8x4 micro-tile ---------------
// C[M,N] = act(A[M,K] @ B[K,N] + bias) + add.  ACT: 0=none, 1=exact GELU.
template<int ACT>
__global__ __launch_bounds__(256) void sgemm(
    const float* __restrict__ A, const float* __restrict__ B,
    const float* __restrict__ bias, const float* __restrict__ addp,
    float* __restrict__ C, int M, int N, int K)
{
    __shared__ float As[16][128];
    __shared__ float Bs[16][64];
    int tid = threadIdx.x;
    int m0 = blockIdx.y * 128;
    int n0 = blockIdx.x * 64;
    int ty = tid >> 4, tx = tid & 15;

    float acc[8][4];
    #pragma unroll
    for (int i = 0; i < 8; i++)
        #pragma unroll
        for (int j = 0; j < 4; j++) acc[i][j] = 0.f;

    for (int k0 = 0; k0 < K; k0 += 16) {
        // A tile: 128 rows x 16 cols  (512 float4, 2 per thread)
        #pragma unroll
        for (int i = 0; i < 2; i++) {
            int idx = tid + i*256;
            int row = idx >> 2;
            int kq  = (idx & 3) * 4;
            float4 v = *(const float4*)(A + (size_t)(m0+row)*K + k0 + kq);
            As[kq+0][row] = v.x; As[kq+1][row] = v.y;
            As[kq+2][row] = v.z; As[kq+3][row] = v.w;
        }
        // B tile: 16 rows x 64 cols  (256 float4, 1 per thread)
        {
            int krow = tid >> 4;
            int nq   = (tid & 15) * 4;
            float4 v = *(const float4*)(B + (size_t)(k0+krow)*N + n0 + nq);
            *(float4*)&Bs[krow][nq] = v;
        }
        __syncthreads();
        #pragma unroll
        for (int k = 0; k < 16; k++) {
            float a[8], b[4];
            #pragma unroll
            for (int i = 0; i < 8; i++) a[i] = As[k][ty*8 + i];
            #pragma unroll
            for (int j = 0; j < 4; j++) b[j] = Bs[k][tx*4 + j];
            #pragma unroll
            for (int i = 0; i < 8; i++)
                #pragma unroll
                for (int j = 0; j < 4; j++)
                    acc[i][j] = fmaf(a[i], b[j], acc[i][j]);
        }
        __syncthreads();
    }

    #pragma unroll
    for (int i = 0; i < 8; i++) {
        int m = m0 + ty*8 + i;
        #pragma unroll
        for (int j = 0; j < 4; j++) {
            int n = n0 + tx*4 + j;
            float v = acc[i][j];
            if (bias) v += bias[n];
            if (ACT == 1) v = 0.5f * v * (1.f + erff(v * 0.70710678118654752f));
            if (addp) v += addp[(size_t)m*N + n];
            C[(size_t)m*N + n] = v;
        }
    }
}

// ---------------- minGRU scans: forward (dir 0) and backward (dir 1) -----
__device__ __forceinline__ float softplusf(float x) {
    return (x > 0.f) ? x + log1pf(expf(-x)) : log1pf(expf(x));
}

__global__ __launch_bounds__(256) void scan_kernel(
    const float* __restrict__ hg1, const float* __restrict__ hg2,
    float* __restrict__ e1, float* __restrict__ e2)
{
    int idx = blockIdx.x * blockDim.x + threadIdx.x;   // 0 .. 2*NB*DIC-1
    int dir = idx / (NB*DIC);
    int r   = idx % (NB*DIC);
    int n   = r / DIC;
    int c   = r % DIC;
    const float* hg = dir ? hg2 : hg1;
    float*       e  = dir ? e2  : e1;
    const size_t base = (size_t)n * SEQ * (2*DIC);
    const size_t ebase = (size_t)n * SEQ * DIC;

    float a = 0.f, L = -INFINITY;
    int t0  = dir ? SEQ-1 : 0;
    int dt  = dir ? -1 : 1;
    for (int s = 0; s < SEQ; s++) {
        int t = t0 + s*dt;
        size_t row = base + (size_t)t * (2*DIC);
        float hid  = hg[row + c];
        float gate = hg[row + DIC + c];
        float lc = -softplusf(gate);                       // log coeff
        float lg = (hid >= 0.f) ? logf(hid + 0.5f) : -softplusf(-hid);
        float lv = -softplusf(-gate) + lg;                 // log value
        a += lc;
        float z  = lv - a;
        float mx = fmaxf(L, z);
        float d  = fabsf(L - z);
        L = mx + log1pf(expf(-d));                         // logaddexp
        e[ebase + (size_t)t*DIC + c] = expf(a + L);
    }
}

// ---------------- launch -------------------------------------------------
extern "C" void kernel_launch(void* const* d_in, const int* in_sizes, int n_in,
                              void* d_out, int out_size)
{
    const float* x        = (const float*)d_in[0];
    const float* gamma1   = (const float*)d_in[1];
    const float* beta1    = (const float*)d_in[2];
    const float* dwc_w    = (const float*)d_in[3];
    const float* dwc_b    = (const float*)d_in[4];
    const float* gru1_w   = (const float*)d_in[5];
    const float* gru1_out = (const float*)d_in[6];
    const float* gru2_w   = (const float*)d_in[7];
    const float* gru2_out = (const float*)d_in[8];
    const float* gamma2   = (const float*)d_in[9];
    const float* beta2    = (const float*)d_in[10];
    const float* p1_w     = (const float*)d_in[11];
    const float* p1_b     = (const float*)d_in[12];
    const float* p2_w     = (const float*)d_in[13];
    const float* p2_b     = (const float*)d_in[14];
    float* out = (float*)d_out;

    float *xn, *xs, *hg1, *hg2, *e1, *e2, *y, *yn, *yh;
    cudaGetSymbolAddress((void**)&xn,  g_xn);
    cudaGetSymbolAddress((void**)&xs,  g_xs);
    cudaGetSymbolAddress((void**)&hg1, g_hg1);
    cudaGetSymbolAddress((void**)&hg2, g_hg2);
    cudaGetSymbolAddress((void**)&e1,  g_e1);
    cudaGetSymbolAddress((void**)&e2,  g_e2);
    cudaGetSymbolAddress((void**)&y,   g_y);
    cudaGetSymbolAddress((void**)&yn,  g_yn);
    cudaGetSymbolAddress((void**)&yh,  g_yh);

    // 1. LN1
    ln_kernel<<<(TOK*32 + 255)/256, 256>>>(x, gamma1, beta1, xn, TOK);
    // 2. depthwise conv 3x3
    dwconv_kernel<<<(TOK*DIMC + 255)/256, 256>>>(xn, dwc_w, dwc_b, xs);
    // 3. GRU input projections: hg = xs @ W  (M=32768, N=1536, K=384)
    {
        dim3 g(2*DIC/64, TOK/128);
        sgemm<0><<<g, 256>>>(xs, gru1_w, nullptr, nullptr, hg1, TOK, 2*DIC, DIMC);
        sgemm<0><<<g, 256>>>(xs, gru2_w, nullptr, nullptr, hg2, TOK, 2*DIC, DIMC);
    }
    // 4. forward + backward minGRU scans
    scan_kernel<<<(2*NB*DIC)/256, 256>>>(hg1, hg2, e1, e2);
    // 5. output projections + residual: y = e1@W1o + x; y += e2@W2o
    {
        dim3 g(DIMC/64, TOK/128);
        sgemm<0><<<g, 256>>>(e1, gru1_out, nullptr, x, y, TOK, DIMC, DIC);
        sgemm<0><<<g, 256>>>(e2, gru2_out, nullptr, y, y, TOK, DIMC, DIC);
    }
    // 6. LN2
    ln_kernel<<<(TOK*32 + 255)/256, 256>>>(y, gamma2, beta2, yn, TOK);
    // 7. MLP up + exact GELU
    {
        dim3 g(MLPD/64, TOK/128);
        sgemm<1><<<g, 256>>>(yn, p1_w, p1_b, nullptr, yh, TOK, MLPD, DIMC);
    }
    // 8. MLP down + bias + residual -> out
    {
        dim3 g(DIMC/64, TOK/128);
        sgemm<0><<<g, 256>>>(yh, p2_w, p2_b, y, out, TOK, DIMC, MLPD);
    }
}

// round 3
// speedup vs baseline: 1.4491x; 1.4491x over previous
#include <cuda_runtime.h>
#include <math.h>
#include <stdint.h>

// ---------------- problem constants (fixed by reference) ----------------
#define NB    32
#define HH    32
#define WW    32
#define SEQ   1024          // H*W
#define DIMC  384
#define DIC   768           // 2*DIM
#define MLPD  1536          // 4*DIM
#define TOK   (NB*SEQ)      // 32768 tokens

// ---------------- scratch (device globals; no runtime alloc) ------------
__device__ float g_xn [(size_t)TOK*DIMC];
__device__ float g_xs [(size_t)TOK*DIMC];
__device__ float g_hg1[(size_t)TOK*2*DIC];
__device__ float g_hg2[(size_t)TOK*2*DIC];
__device__ float g_e1 [(size_t)TOK*DIC];
__device__ float g_e2 [(size_t)TOK*DIC];
__device__ float g_y  [(size_t)TOK*DIMC];
__device__ float g_yn [(size_t)TOK*DIMC];
__device__ float g_yh [(size_t)TOK*MLPD];

// ---------------- layer norm: one warp per token row ---------------------
__global__ __launch_bounds__(256) void ln_kernel(
    const float* __restrict__ x, const float* __restrict__ gamma,
    const float* __restrict__ beta, float* __restrict__ out, int rows)
{
    int gw   = (blockIdx.x * blockDim.x + threadIdx.x) >> 5;
    int lane = threadIdx.x & 31;
    if (gw >= rows) return;
    const float* xr = x + (size_t)gw * DIMC;
    float s = 0.f, s2 = 0.f;
    #pragma unroll
    for (int i = lane; i < DIMC; i += 32) { float v = xr[i]; s += v; s2 += v*v; }
    #pragma unroll
    for (int o = 16; o; o >>= 1) {
        s  += __shfl_xor_sync(0xffffffffu, s,  o);
        s2 += __shfl_xor_sync(0xffffffffu, s2, o);
    }
    float mu  = s * (1.f/DIMC);
    float var = s2 * (1.f/DIMC) - mu*mu;
    float inv = rsqrtf(var + 1e-5f);
    float* orow = out + (size_t)gw * DIMC;
    #pragma unroll
    for (int i = lane; i < DIMC; i += 32)
        orow[i] = (xr[i] - mu) * inv * gamma[i] + beta[i];
}

// ---------------- depthwise 3x3 conv, NHWC, pad=1 ------------------------
__global__ __launch_bounds__(256) void dwconv_kernel(
    const float* __restrict__ xn, const float* __restrict__ w,
    const float* __restrict__ b, float* __restrict__ xs)
{
    int idx = blockIdx.x * blockDim.x + threadIdx.x;       // 0 .. TOK*DIMC-1
    if (idx >= TOK*DIMC) return;
    int c = idx % DIMC;
    int p = idx / DIMC;
    int xq = p % WW;
    int yq = (p / WW) % HH;
    int n  = p / SEQ;
    float acc = b[c];
    const float* wc = w + c * 9;
    #pragma unroll
    for (int ky = 0; ky < 3; ky++) {
        int yy = yq + ky - 1;
        if (yy < 0 || yy >= HH) continue;
        #pragma unroll
        for (int kx = 0; kx < 3; kx++) {
            int xx = xq + kx - 1;
            if (xx < 0 || xx >= WW) continue;
            acc += wc[ky*3+kx] * xn[((size_t)n*SEQ + yy*WW + xx)*DIMC + c];
        }
    }
    xs[idx] = acc;
}

// ---------------- tf32 tensor-core GEMM ----------------------------------
// C[M,N] = act(A[M,K] @ B[K,N] + bias) + add.  ACT: 0=none, 1=exact GELU.
// Block tile 128x64x16, 8 warps (4 m x 2 n), warp tile 32x32 (2x4 m16n8k8).
__device__ __forceinline__ uint32_t f2tf32(float f) {
    uint32_t u;
    asm("cvt.rna.tf32.f32 %0, %1;" : "=r"(u) : "f"(f));
    return u;
}

#define MMA_TF32(d, a0,a1,a2,a3, b0,b1)                                     \
    asm volatile(                                                           \
        "mma.sync.aligned.m16n8k8.row.col.f32.tf32.tf32.f32 "               \
        "{%0,%1,%2,%3}, {%4,%5,%6,%7}, {%8,%9}, {%0,%1,%2,%3};\n"           \
        : "+f"(d[0]), "+f"(d[1]), "+f"(d[2]), "+f"(d[3])                    \
        : "r"(a0), "r"(a1), "r"(a2), "r"(a3), "r"(b0), "r"(b1))

#define APAD 136   // 128 + 8 : k-row pitch -> bank = 8*tig + gid (conflict-free)
#define BPAD 72    // 64 + 8

template<int ACT>
__global__ __launch_bounds__(256) void tgemm(
    const float* __restrict__ A, const float* __restrict__ B,
    const float* __restrict__ bias, const float* __restrict__ addp,
    float* __restrict__ C, int M, int N, int K)
{
    __shared__ uint32_t As[16 * APAD];   // [k][m]
    __shared__ uint32_t Bs[16 * BPAD];   // [k][n]
    int tid  = threadIdx.x;
    int wid  = tid >> 5, lane = tid & 31;
    int wm   = wid & 3;          // warp m index (4)
    int wn   = wid >> 2;         // warp n index (2)
    int gid  = lane >> 2;        // 0..7
    int tig  = lane & 3;         // 0..3
    int m0   = blockIdx.y * 128;
    int n0   = blockIdx.x * 64;

    float acc[2][4][4];
    #pragma unroll
    for (int mi = 0; mi < 2; mi++)
        #pragma unroll
        for (int ni = 0; ni < 4; ni++)
            #pragma unroll
            for (int q = 0; q < 4; q++) acc[mi][ni][q] = 0.f;

    for (int k0 = 0; k0 < K; k0 += 16) {
        // A tile: 128 rows x 16 k (512 float4, 2 per thread)
        #pragma unroll
        for (int i = 0; i < 2; i++) {
            int idx = tid + i*256;
            int row = idx >> 2;
            int kq  = (idx & 3) * 4;
            float4 v = *(const float4*)(A + (size_t)(m0+row)*K + k0 + kq);
            As[(kq+0)*APAD + row] = f2tf32(v.x);
            As[(kq+1)*APAD + row] = f2tf32(v.y);
            As[(kq+2)*APAD + row] = f2tf32(v.z);
            As[(kq+3)*APAD + row] = f2tf32(v.w);
        }
        // B tile: 16 k x 64 n (256 float4, 1 per thread)
        {
            int krow = tid >> 4;
            int nq   = (tid & 15) * 4;
            float4 v = *(const float4*)(B + (size_t)(k0+krow)*N + n0 + nq);
            Bs[krow*BPAD + nq+0] = f2tf32(v.x);
            Bs[krow*BPAD + nq+1] = f2tf32(v.y);
            Bs[krow*BPAD + nq+2] = f2tf32(v.z);
            Bs[krow*BPAD + nq+3] = f2tf32(v.w);
        }
        __syncthreads();
        #pragma unroll
        for (int ks = 0; ks < 2; ks++) {
            // A fragments: a0=(gid,tig) a1=(gid+8,tig) a2=(gid,tig+4) a3=(gid+8,tig+4)
            uint32_t af[2][4];
            #pragma unroll
            for (int mi = 0; mi < 2; mi++) {
                int r = wm*32 + mi*16 + gid;
                af[mi][0] = As[(ks*8+tig  )*APAD + r    ];
                af[mi][1] = As[(ks*8+tig  )*APAD + r + 8];
                af[mi][2] = As[(ks*8+tig+4)*APAD + r    ];
                af[mi][3] = As[(ks*8+tig+4)*APAD + r + 8];
            }
            // B fragments: b0=(k=tig, n=gid) b1=(k=tig+4, n=gid)
            uint32_t bf[4][2];
            #pragma unroll
            for (int ni = 0; ni < 4; ni++) {
                int c = wn*32 + ni*8 + gid;
                bf[ni][0] = Bs[(ks*8+tig  )*BPAD + c];
                bf[ni][1] = Bs[(ks*8+tig+4)*BPAD + c];
            }
            #pragma unroll
            for (int mi = 0; mi < 2; mi++)
                #pragma unroll
                for (int ni = 0; ni < 4; ni++)
                    MMA_TF32(acc[mi][ni], af[mi][0], af[mi][1], af[mi][2], af[mi][3],
                             bf[ni][0], bf[ni][1]);
        }
        __syncthreads();
    }

    // epilogue: c0=(gid,2tig) c1=(gid,2tig+1) c2=(gid+8,2tig) c3=(gid+8,2tig+1)
    #pragma unroll
    for (int mi = 0; mi < 2; mi++) {
        int r0 = m0 + wm*32 + mi*16 + gid;
        #pragma unroll
        for (int ni = 0; ni < 4; ni++) {
            int cn = n0 + wn*32 + ni*8 + tig*2;
            #pragma unroll
            for (int half = 0; half < 2; half++) {
                int r = r0 + half*8;
                float v0 = acc[mi][ni][half*2+0];
                float v1 = acc[mi][ni][half*2+1];
                if (bias) { v0 += bias[cn]; v1 += bias[cn+1]; }
                if (ACT == 1) {
                    v0 = 0.5f * v0 * (1.f + erff(v0 * 0.70710678118654752f));
                    v1 = 0.5f * v1 * (1.f + erff(v1 * 0.70710678118654752f));
                }
                if (addp) {
                    float2 ad = *(const float2*)(addp + (size_t)r*N + cn);
                    v0 += ad.x; v1 += ad.y;
                }
                float2 ov; ov.x = v0; ov.y = v1;
                *(float2*)(C + (size_t)r*N + cn) = ov;
            }
        }
    }
}

// ---------------- minGRU scans: forward (dir 0) and backward (dir 1) -----
__device__ __forceinline__ float softplus_fast(float x) {
    // log(1+exp(x)), stable; log-space O(1) quantities -> fast intrinsics fine
    float ax = fabsf(x);
    float sp = __logf(1.f + __expf(-ax));
    return (x > 0.f) ? x + sp : sp;
}

__global__ __launch_bounds__(256) void scan_kernel(
    const float* __restrict__ hg1, const float* __restrict__ hg2,
    float* __restrict__ e1, float* __restrict__ e2)
{
    int idx = blockIdx.x * blockDim.x + threadIdx.x;   // 0 .. 2*NB*DIC-1
    int dir = idx / (NB*DIC);
    int r   = idx % (NB*DIC);
    int n   = r / DIC;
    int c   = r % DIC;
    const float* hg = dir ? hg2 : hg1;
    float*       e  = dir ? e2  : e1;
    const size_t base  = (size_t)n * SEQ * (2*DIC);
    const size_t ebase = (size_t)n * SEQ * DIC;

    float a = 0.f, L = -INFINITY;
    int t0  = dir ? SEQ-1 : 0;
    int dt  = dir ? -1 : 1;
    for (int s = 0; s < SEQ; s++) {
        int t = t0 + s*dt;
        size_t row = base + (size_t)t * (2*DIC);
        float hid  = hg[row + c];
        float gate = hg[row + DIC + c];
        float lc = -softplus_fast(gate);                       // log coeff
        float lg = (hid >= 0.f) ? __logf(hid + 0.5f) : -softplus_fast(-hid);
        float lv = -softplus_fast(-gate) + lg;                 // log value
        a += lc;
        float z  = lv - a;
        float mx = fmaxf(L, z);
        float d  = fabsf(L - z);
        L = mx + __logf(1.f + __expf(-d));                     // logaddexp
        e[ebase + (size_t)t*DIC + c] = __expf(a + L);
    }
}

// ---------------- launch -------------------------------------------------
extern "C" void kernel_launch(void* const* d_in, const int* in_sizes, int n_in,
                              void* d_out, int out_size)
{
    const float* x        = (const float*)d_in[0];
    const float* gamma1   = (const float*)d_in[1];
    const float* beta1    = (const float*)d_in[2];
    const float* dwc_w    = (const float*)d_in[3];
    const float* dwc_b    = (const float*)d_in[4];
    const float* gru1_w   = (const float*)d_in[5];
    const float* gru1_out = (const float*)d_in[6];
    const float* gru2_w   = (const float*)d_in[7];
    const float* gru2_out = (const float*)d_in[8];
    const float* gamma2   = (const float*)d_in[9];
    const float* beta2    = (const float*)d_in[10];
    const float* p1_w     = (const float*)d_in[11];
    const float* p1_b     = (const float*)d_in[12];
    const float* p2_w     = (const float*)d_in[13];
    const float* p2_b     = (const float*)d_in[14];
    float* out = (float*)d_out;

    float *xn, *xs, *hg1, *hg2, *e1, *e2, *y, *yn, *yh;
    cudaGetSymbolAddress((void**)&xn,  g_xn);
    cudaGetSymbolAddress((void**)&xs,  g_xs);
    cudaGetSymbolAddress((void**)&hg1, g_hg1);
    cudaGetSymbolAddress((void**)&hg2, g_hg2);
    cudaGetSymbolAddress((void**)&e1,  g_e1);
    cudaGetSymbolAddress((void**)&e2,  g_e2);
    cudaGetSymbolAddress((void**)&y,   g_y);
    cudaGetSymbolAddress((void**)&yn,  g_yn);
    cudaGetSymbolAddress((void**)&yh,  g_yh);

    // 1. LN1
    ln_kernel<<<(TOK*32 + 255)/256, 256>>>(x, gamma1, beta1, xn, TOK);
    // 2. depthwise conv 3x3
    dwconv_kernel<<<(TOK*DIMC + 255)/256, 256>>>(xn, dwc_w, dwc_b, xs);
    // 3. GRU input projections: hg = xs @ W  (M=32768, N=1536, K=384)
    {
        dim3 g(2*DIC/64, TOK/128);
        tgemm<0><<<g, 256>>>(xs, gru1_w, nullptr, nullptr, hg1, TOK, 2*DIC, DIMC);
        tgemm<0><<<g, 256>>>(xs, gru2_w, nullptr, nullptr, hg2, TOK, 2*DIC, DIMC);
    }
    // 4. forward + backward minGRU scans
    scan_kernel<<<(2*NB*DIC)/256, 256>>>(hg1, hg2, e1, e2);
    // 5. output projections + residual: y = e1@W1o + x; y += e2@W2o
    {
        dim3 g(DIMC/64, TOK/128);
        tgemm<0><<<g, 256>>>(e1, gru1_out, nullptr, x, y, TOK, DIMC, DIC);
        tgemm<0><<<g, 256>>>(e2, gru2_out, nullptr, y, y, TOK, DIMC, DIC);
    }
    // 6. LN2
    ln_kernel<<<(TOK*32 + 255)/256, 256>>>(y, gamma2, beta2, yn, TOK);
    // 7. MLP up + exact GELU
    {
        dim3 g(MLPD/64, TOK/128);
        tgemm<1><<<g, 256>>>(yn, p1_w, p1_b, nullptr, yh, TOK, MLPD, DIMC);
    }
    // 8. MLP down + bias + residual -> out
    {
        dim3 g(DIMC/64, TOK/128);
        tgemm<0><<<g, 256>>>(yh, p2_w, p2_b, y, out, TOK, DIMC, MLPD);
    }
}

// round 5
// speedup vs baseline: 2.5985x; 1.7932x over previous
#include <cuda_runtime.h>
#include <math.h>
#include <stdint.h>

// ---------------- problem constants (fixed by reference) ----------------
#define NB    32
#define HH    32
#define WW    32
#define SEQ   1024          // H*W
#define DIMC  384
#define DIC   768           // 2*DIM
#define MLPD  1536          // 4*DIM
#define TOK   (NB*SEQ)      // 32768 tokens

// ---------------- scratch (device globals; no runtime alloc) ------------
__device__ float g_xn [(size_t)TOK*DIMC];
__device__ float g_xs [(size_t)TOK*DIMC];
__device__ float g_hg1[(size_t)TOK*2*DIC];
__device__ float g_hg2[(size_t)TOK*2*DIC];
__device__ float g_e1 [(size_t)TOK*DIC];
__device__ float g_e2 [(size_t)TOK*DIC];
__device__ float g_y  [(size_t)TOK*DIMC];
__device__ float g_yn [(size_t)TOK*DIMC];
__device__ float g_yh [(size_t)TOK*MLPD];
// transposed weights (K-major, [N][K]) for the B operand
__device__ float g_w1T [(size_t)DIMC*2*DIC];
__device__ float g_w2T [(size_t)DIMC*2*DIC];
__device__ float g_o1T [(size_t)DIC*DIMC];
__device__ float g_o2T [(size_t)DIC*DIMC];
__device__ float g_p1T [(size_t)DIMC*MLPD];
__device__ float g_p2T [(size_t)MLPD*DIMC];

// ================= small helpers ========================================
__device__ __forceinline__ uint32_t smem_to_u32(const void* p) {
    uint32_t a;
    asm("{ .reg .u64 t; cvta.to.shared.u64 t, %1; cvt.u32.u64 %0, t; }"
        : "=r"(a) : "l"(p));
    return a;
}
__device__ __forceinline__ uint32_t lds32(uint32_t a) {
    uint32_t v;
    asm volatile("ld.shared.b32 %0, [%1];" : "=r"(v) : "r"(a));
    return v;
}
#define CP_ASYNC16(dst, src) \
    asm volatile("cp.async.cg.shared.global [%0], [%1], 16;" \
                 :: "r"(dst), "l"(src) : "memory")
#define CP_COMMIT() asm volatile("cp.async.commit_group;" ::: "memory")
#define CP_WAIT(n)  asm volatile("cp.async.wait_group %0;" :: "n"(n) : "memory")

#define MMA_TF32(d, a0,a1,a2,a3, b0,b1)                                     \
    asm volatile(                                                           \
        "mma.sync.aligned.m16n8k8.row.col.f32.tf32.tf32.f32 "               \
        "{%0,%1,%2,%3}, {%4,%5,%6,%7}, {%8,%9}, {%0,%1,%2,%3};\n"           \
        : "+f"(d[0]), "+f"(d[1]), "+f"(d[2]), "+f"(d[3])                    \
        : "r"(a0), "r"(a1), "r"(a2), "r"(a3), "r"(b0), "r"(b1))

// ---------------- layer norm: one warp per token row ---------------------
__global__ __launch_bounds__(256) void ln_kernel(
    const float* __restrict__ x, const float* __restrict__ gamma,
    const float* __restrict__ beta, float* __restrict__ out, int rows)
{
    int gw   = (blockIdx.x * blockDim.x + threadIdx.x) >> 5;
    int lane = threadIdx.x & 31;
    if (gw >= rows) return;
    const float* xr = x + (size_t)gw * DIMC;
    float s = 0.f, s2 = 0.f;
    #pragma unroll
    for (int i = lane; i < DIMC; i += 32) { float v = xr[i]; s += v; s2 += v*v; }
    #pragma unroll
    for (int o = 16; o; o >>= 1) {
        s  += __shfl_xor_sync(0xffffffffu, s,  o);
        s2 += __shfl_xor_sync(0xffffffffu, s2, o);
    }
    float mu  = s * (1.f/DIMC);
    float var = s2 * (1.f/DIMC) - mu*mu;
    float inv = rsqrtf(var + 1e-5f);
    float* orow = out + (size_t)gw * DIMC;
    #pragma unroll
    for (int i = lane; i < DIMC; i += 32)
        orow[i] = (xr[i] - mu) * inv * gamma[i] + beta[i];
}

// ---------------- depthwise 3x3 conv, NHWC, pad=1 ------------------------
__global__ __launch_bounds__(256) void dwconv_kernel(
    const float* __restrict__ xn, const float* __restrict__ w,
    const float* __restrict__ b, float* __restrict__ xs)
{
    int idx = blockIdx.x * blockDim.x + threadIdx.x;
    if (idx >= TOK*DIMC) return;
    int c = idx % DIMC;
    int p = idx / DIMC;
    int xq = p % WW;
    int yq = (p / WW) % HH;
    int n  = p / SEQ;
    float acc = b[c];
    const float* wc = w + c * 9;
    #pragma unroll
    for (int ky = 0; ky < 3; ky++) {
        int yy = yq + ky - 1;
        if (yy < 0 || yy >= HH) continue;
        #pragma unroll
        for (int kx = 0; kx < 3; kx++) {
            int xx = xq + kx - 1;
            if (xx < 0 || xx >= WW) continue;
            acc += wc[ky*3+kx] * xn[((size_t)n*SEQ + yy*WW + xx)*DIMC + c];
        }
    }
    xs[idx] = acc;
}

// ---------------- weight transpose [K,N] -> [N,K] ------------------------
__global__ __launch_bounds__(256) void transpose_kernel(
    const float* __restrict__ in, float* __restrict__ out, int K, int N)
{
    __shared__ float t[32][33];
    int kb = blockIdx.x * 32, nb = blockIdx.y * 32;
    int tx = threadIdx.x & 31, ty = threadIdx.x >> 5;   // 32 x 8
    #pragma unroll
    for (int i = 0; i < 32; i += 8)
        t[ty+i][tx] = in[(size_t)(kb+ty+i)*N + nb+tx];
    __syncthreads();
    #pragma unroll
    for (int i = 0; i < 32; i += 8)
        out[(size_t)(nb+ty+i)*K + kb+tx] = t[tx][ty+i];
}

// ---------------- tf32 tensor GEMM, cp.async 3-stage pipeline ------------
// C[M,N] = act(A[M,K] @ Bt[N,K]^T + bias) + add.  ACT: 0=none, 1=exact GELU.
// CTA tile 128 x NT, K-tile 16. 8 warps as 2(m) x 4(n); warp tile 64 x NT/4.
// smem layout per stage: A[128][16] rows at 80B pitch, then B[NT][16] same.
#define STAGES 3
#define APITCH 80
#define ABYTES (128*APITCH)

template<int ACT, int NT>
__global__ __launch_bounds__(256, 1) void tc_gemm(
    const float* __restrict__ A, const float* __restrict__ Bt,
    const float* __restrict__ bias, const float* __restrict__ addp,
    float* __restrict__ C, int M, int N, int K)
{
    constexpr int NTILE = NT / 32;           // n8 tiles per warp (8 or 4)
    constexpr int BBYTES = NT * APITCH;
    constexpr int STB = ABYTES + BBYTES;
    extern __shared__ char smem[];
    const uint32_t sbase = smem_to_u32(smem);

    const int tid  = threadIdx.x;
    const int wid  = tid >> 5;
    const int lane = tid & 31;
    const int wm   = wid & 1;                // warp m (2)
    const int wn   = wid >> 1;               // warp n (4)
    const int gid  = lane >> 2;              // 0..7
    const int tig  = lane & 3;               // 0..3
    const int m0   = blockIdx.y * 128;
    const int n0   = blockIdx.x * NT;
    const int nk   = K >> 4;

    float acc[4][NTILE][4];
    #pragma unroll
    for (int mi = 0; mi < 4; mi++)
        #pragma unroll
        for (int ni = 0; ni < NTILE; ni++)
            #pragma unroll
            for (int q = 0; q < 4; q++) acc[mi][ni][q] = 0.f;

    // ---- tile loader: global -> smem stage via cp.async (16B chunks) ----
    auto load_tile = [&](int i) {
        uint32_t sa = sbase + (i % STAGES) * STB;
        uint32_t sb = sa + ABYTES;
        const float* Ag = A  + (size_t)m0 * K + i*16;
        const float* Bg = Bt + (size_t)n0 * K + i*16;
        #pragma unroll
        for (int t = 0; t < 2; t++) {                 // A: 512 chunks
            int f = tid + t*256;
            int r = f >> 2, kc = f & 3;
            CP_ASYNC16(sa + r*APITCH + kc*16, Ag + (size_t)r*K + kc*4);
        }
        #pragma unroll
        for (int t = 0; t < NT/64; t++) {             // B: NT*4 chunks
            int f = tid + t*256;
            int r = f >> 2, kc = f & 3;
            CP_ASYNC16(sb + r*APITCH + kc*16, Bg + (size_t)r*K + kc*4);
        }
    };

    #pragma unroll
    for (int s = 0; s < STAGES-1; s++) { if (s < nk) load_tile(s); CP_COMMIT(); }

    for (int i = 0; i < nk; i++) {
        CP_WAIT(STAGES-2);
        __syncthreads();
        int inext = i + STAGES - 1;
        if (inext < nk) load_tile(inext);
        CP_COMMIT();

        uint32_t sa = sbase + (i % STAGES) * STB;
        uint32_t sb = sa + ABYTES;
        #pragma unroll
        for (int ks = 0; ks < 2; ks++) {
            uint32_t af[4][4];
            #pragma unroll
            for (int mi = 0; mi < 4; mi++) {
                uint32_t ba = sa + (wm*64 + mi*16 + gid)*APITCH + (ks*8+tig)*4;
                af[mi][0] = lds32(ba);
                af[mi][1] = lds32(ba + 8*APITCH);
                af[mi][2] = lds32(ba + 16);
                af[mi][3] = lds32(ba + 8*APITCH + 16);
            }
            uint32_t bf[NTILE][2];
            #pragma unroll
            for (int ni = 0; ni < NTILE; ni++) {
                uint32_t bb = sb + (wn*(NT/4) + ni*8 + gid)*APITCH + (ks*8+tig)*4;
                bf[ni][0] = lds32(bb);
                bf[ni][1] = lds32(bb + 16);
            }
            #pragma unroll
            for (int mi = 0; mi < 4; mi++)
                #pragma unroll
                for (int ni = 0; ni < NTILE; ni++)
                    MMA_TF32(acc[mi][ni], af[mi][0], af[mi][1], af[mi][2], af[mi][3],
                             bf[ni][0], bf[ni][1]);
        }
        __syncthreads();
    }

    // ---- epilogue: c0=(gid,2tig) c1=(gid,2tig+1) c2/c3 at row+8 ----------
    #pragma unroll
    for (int mi = 0; mi < 4; mi++) {
        int r0 = m0 + wm*64 + mi*16 + gid;
        #pragma unroll
        for (int ni = 0; ni < NTILE; ni++) {
            int cn = n0 + wn*(NT/4) + ni*8 + tig*2;
            #pragma unroll
            for (int half = 0; half < 2; half++) {
                int r = r0 + half*8;
                float v0 = acc[mi][ni][half*2+0];
                float v1 = acc[mi][ni][half*2+1];
                if (bias) { v0 += bias[cn]; v1 += bias[cn+1]; }
                if (ACT == 1) {
                    v0 = 0.5f * v0 * (1.f + erff(v0 * 0.70710678118654752f));
                    v1 = 0.5f * v1 * (1.f + erff(v1 * 0.70710678118654752f));
                }
                if (addp) {
                    float2 ad = *(const float2*)(addp + (size_t)r*N + cn);
                    v0 += ad.x; v1 += ad.y;
                }
                float2 ov; ov.x = v0; ov.y = v1;
                *(float2*)(C + (size_t)r*N + cn) = ov;
            }
        }
    }
}

// ---------------- minGRU scans: forward (dir 0) and backward (dir 1) -----
__device__ __forceinline__ float softplus_fast(float x) {
    float ax = fabsf(x);
    float sp = __logf(1.f + __expf(-ax));
    return (x > 0.f) ? x + sp : sp;
}

__global__ __launch_bounds__(256) void scan_kernel(
    const float* __restrict__ hg1, const float* __restrict__ hg2,
    float* __restrict__ e1, float* __restrict__ e2)
{
    int idx = blockIdx.x * blockDim.x + threadIdx.x;   // 0 .. 2*NB*DIC-1
    int dir = idx / (NB*DIC);
    int r   = idx % (NB*DIC);
    int n   = r / DIC;
    int c   = r % DIC;
    const float* hg = dir ? hg2 : hg1;
    float*       e  = dir ? e2  : e1;
    const size_t base  = (size_t)n * SEQ * (2*DIC);
    const size_t ebase = (size_t)n * SEQ * DIC;

    float a = 0.f, L = -INFINITY;
    int t0  = dir ? SEQ-1 : 0;
    int dt  = dir ? -1 : 1;
    for (int s = 0; s < SEQ; s++) {
        int t = t0 + s*dt;
        size_t row = base + (size_t)t * (2*DIC);
        float hid  = hg[row + c];
        float gate = hg[row + DIC + c];
        float lc = -softplus_fast(gate);
        float lg = (hid >= 0.f) ? __logf(hid + 0.5f) : -softplus_fast(-hid);
        float lv = -softplus_fast(-gate) + lg;
        a += lc;
        float z  = lv - a;
        float mx = fmaxf(L, z);
        float d  = fabsf(L - z);
        L = mx + __logf(1.f + __expf(-d));
        e[ebase + (size_t)t*DIC + c] = __expf(a + L);
    }
}

// ---------------- launch -------------------------------------------------
extern "C" void kernel_launch(void* const* d_in, const int* in_sizes, int n_in,
                              void* d_out, int out_size)
{
    const float* x        = (const float*)d_in[0];
    const float* gamma1   = (const float*)d_in[1];
    const float* beta1    = (const float*)d_in[2];
    const float* dwc_w    = (const float*)d_in[3];
    const float* dwc_b    = (const float*)d_in[4];
    const float* gru1_w   = (const float*)d_in[5];
    const float* gru1_out = (const float*)d_in[6];
    const float* gru2_w   = (const float*)d_in[7];
    const float* gru2_out = (const float*)d_in[8];
    const float* gamma2   = (const float*)d_in[9];
    const float* beta2    = (const float*)d_in[10];
    const float* p1_w     = (const float*)d_in[11];
    const float* p1_b     = (const float*)d_in[12];
    const float* p2_w     = (const float*)d_in[13];
    const float* p2_b     = (const float*)d_in[14];
    float* out = (float*)d_out;

    float *xn, *xs, *hg1, *hg2, *e1, *e2, *y, *yn, *yh;
    float *w1T, *w2T, *o1T, *o2T, *p1T, *p2T;
    cudaGetSymbolAddress((void**)&xn,  g_xn);
    cudaGetSymbolAddress((void**)&xs,  g_xs);
    cudaGetSymbolAddress((void**)&hg1, g_hg1);
    cudaGetSymbolAddress((void**)&hg2, g_hg2);
    cudaGetSymbolAddress((void**)&e1,  g_e1);
    cudaGetSymbolAddress((void**)&e2,  g_e2);
    cudaGetSymbolAddress((void**)&y,   g_y);
    cudaGetSymbolAddress((void**)&yn,  g_yn);
    cudaGetSymbolAddress((void**)&yh,  g_yh);
    cudaGetSymbolAddress((void**)&w1T, g_w1T);
    cudaGetSymbolAddress((void**)&w2T, g_w2T);
    cudaGetSymbolAddress((void**)&o1T, g_o1T);
    cudaGetSymbolAddress((void**)&o2T, g_o2T);
    cudaGetSymbolAddress((void**)&p1T, g_p1T);
    cudaGetSymbolAddress((void**)&p2T, g_p2T);

    const int SMEM_256 = STAGES * (ABYTES + 256*APITCH);   // 3*(10240+20480)=92160
    const int SMEM_128 = STAGES * (ABYTES + 128*APITCH);   // 3*(10240+10240)=61440
    cudaFuncSetAttribute(tc_gemm<0,256>, cudaFuncAttributeMaxDynamicSharedMemorySize, SMEM_256);
    cudaFuncSetAttribute(tc_gemm<1,256>, cudaFuncAttributeMaxDynamicSharedMemorySize, SMEM_256);
    cudaFuncSetAttribute(tc_gemm<0,128>, cudaFuncAttributeMaxDynamicSharedMemorySize, SMEM_128);

    // 0. weight transposes (K-major B operand)
    transpose_kernel<<<dim3(DIMC/32, 2*DIC/32), 256>>>(gru1_w,   w1T, DIMC, 2*DIC);
    transpose_kernel<<<dim3(DIMC/32, 2*DIC/32), 256>>>(gru2_w,   w2T, DIMC, 2*DIC);
    transpose_kernel<<<dim3(DIC/32,  DIMC/32),  256>>>(gru1_out, o1T, DIC,  DIMC);
    transpose_kernel<<<dim3(DIC/32,  DIMC/32),  256>>>(gru2_out, o2T, DIC,  DIMC);
    transpose_kernel<<<dim3(DIMC/32, MLPD/32),  256>>>(p1_w,     p1T, DIMC, MLPD);
    transpose_kernel<<<dim3(MLPD/32, DIMC/32),  256>>>(p2_w,     p2T, MLPD, DIMC);

    // 1. LN1
    ln_kernel<<<(TOK*32 + 255)/256, 256>>>(x, gamma1, beta1, xn, TOK);
    // 2. depthwise conv 3x3
    dwconv_kernel<<<(TOK*DIMC + 255)/256, 256>>>(xn, dwc_w, dwc_b, xs);
    // 3. GRU input projections: hg = xs @ W  (M=32768, N=1536, K=384)
    {
        dim3 g((2*DIC)/256, TOK/128);
        tc_gemm<0,256><<<g, 256, SMEM_256>>>(xs, w1T, nullptr, nullptr, hg1, TOK, 2*DIC, DIMC);
        tc_gemm<0,256><<<g, 256, SMEM_256>>>(xs, w2T, nullptr, nullptr, hg2, TOK, 2*DIC, DIMC);
    }
    // 4. forward + backward minGRU scans
    scan_kernel<<<(2*NB*DIC)/256, 256>>>(hg1, hg2, e1, e2);
    // 5. output projections + residual: y = e1@W1o + x; y += e2@W2o
    {
        dim3 g(DIMC/128, TOK/128);
        tc_gemm<0,128><<<g, 256, SMEM_128>>>(e1, o1T, nullptr, x, y, TOK, DIMC, DIC);
        tc_gemm<0,128><<<g, 256, SMEM_128>>>(e2, o2T, nullptr, y, y, TOK, DIMC, DIC);
    }
    // 6. LN2
    ln_kernel<<<(TOK*32 + 255)/256, 256>>>(y, gamma2, beta2, yn, TOK);
    // 7. MLP up + exact GELU
    {
        dim3 g(MLPD/256, TOK/128);
        tc_gemm<1,256><<<g, 256, SMEM_256>>>(yn, p1T, p1_b, nullptr, yh, TOK, MLPD, DIMC);
    }
    // 8. MLP down + bias + residual -> out
    {
        dim3 g(DIMC/128, TOK/128);
        tc_gemm<0,128><<<g, 256, SMEM_128>>>(yh, p2T, p2_b, y, out, TOK, DIMC, MLPD);
    }
}

// round 7
// speedup vs baseline: 2.7218x; 1.0475x over previous
#include <cuda_runtime.h>
#include <math.h>
#include <stdint.h>

// ---------------- problem constants (fixed by reference) ----------------
#define NB    32
#define HH    32
#define WW    32
#define SEQ   1024          // H*W
#define DIMC  384
#define DIC   768           // 2*DIM
#define MLPD  1536          // 4*DIM
#define TOK   (NB*SEQ)      // 32768 tokens

// ---------------- scratch (device globals; no runtime alloc) ------------
__device__ float g_xn [(size_t)TOK*DIMC];
__device__ float g_xs [(size_t)TOK*DIMC];
__device__ float g_hg [(size_t)TOK*3072];      // [tok][dir*1536 + {hid:0-767, gate:768-1535}]
__device__ float g_e1 [(size_t)TOK*DIC];
__device__ float g_e2 [(size_t)TOK*DIC];
__device__ float g_y  [(size_t)TOK*DIMC];
__device__ float g_yn [(size_t)TOK*DIMC];
__device__ float g_yh [(size_t)TOK*MLPD];
// transposed weights (K-major, [N][K]) for the B operand
__device__ float g_wT  [(size_t)3072*DIMC];    // concat(gru1_w^T, gru2_w^T)
__device__ float g_o1T [(size_t)DIC*DIMC];
__device__ float g_o2T [(size_t)DIC*DIMC];
__device__ float g_p1T [(size_t)DIMC*MLPD];
__device__ float g_p2T [(size_t)MLPD*DIMC];

// ================= small helpers ========================================
__device__ __forceinline__ uint32_t smem_to_u32(const void* p) {
    uint32_t a;
    asm("{ .reg .u64 t; cvta.to.shared.u64 t, %1; cvt.u32.u64 %0, t; }"
        : "=r"(a) : "l"(p));
    return a;
}
__device__ __forceinline__ uint32_t lds32(uint32_t a) {
    uint32_t v;
    asm volatile("ld.shared.b32 %0, [%1];" : "=r"(v) : "r"(a));
    return v;
}
#define CP_ASYNC16(dst, src) \
    asm volatile("cp.async.cg.shared.global [%0], [%1], 16;" \
                 :: "r"(dst), "l"(src) : "memory")
#define CP_COMMIT() asm volatile("cp.async.commit_group;" ::: "memory")
#define CP_WAIT(n)  asm volatile("cp.async.wait_group %0;" :: "n"(n) : "memory")

#define MMA_TF32(d, a0,a1,a2,a3, b0,b1)                                     \
    asm volatile(                                                           \
        "mma.sync.aligned.m16n8k8.row.col.f32.tf32.tf32.f32 "               \
        "{%0,%1,%2,%3}, {%4,%5,%6,%7}, {%8,%9}, {%0,%1,%2,%3};\n"           \
        : "+f"(d[0]), "+f"(d[1]), "+f"(d[2]), "+f"(d[3])                    \
        : "r"(a0), "r"(a1), "r"(a2), "r"(a3), "r"(b0), "r"(b1))

// ---------------- layer norm: one warp per token row ---------------------
__global__ __launch_bounds__(256) void ln_kernel(
    const float* __restrict__ x, const float* __restrict__ gamma,
    const float* __restrict__ beta, float* __restrict__ out, int rows)
{
    int gw   = (blockIdx.x * blockDim.x + threadIdx.x) >> 5;
    int lane = threadIdx.x & 31;
    if (gw >= rows) return;
    const float* xr = x + (size_t)gw * DIMC;
    float s = 0.f, s2 = 0.f;
    #pragma unroll
    for (int i = lane; i < DIMC; i += 32) { float v = xr[i]; s += v; s2 += v*v; }
    #pragma unroll
    for (int o = 16; o; o >>= 1) {
        s  += __shfl_xor_sync(0xffffffffu, s,  o);
        s2 += __shfl_xor_sync(0xffffffffu, s2, o);
    }
    float mu  = s * (1.f/DIMC);
    float var = s2 * (1.f/DIMC) - mu*mu;
    float inv = rsqrtf(var + 1e-5f);
    float* orow = out + (size_t)gw * DIMC;
    #pragma unroll
    for (int i = lane; i < DIMC; i += 32)
        orow[i] = (xr[i] - mu) * inv * gamma[i] + beta[i];
}

// ---------------- depthwise 3x3 conv, NHWC, pad=1 ------------------------
__global__ __launch_bounds__(256) void dwconv_kernel(
    const float* __restrict__ xn, const float* __restrict__ w,
    const float* __restrict__ b, float* __restrict__ xs)
{
    int idx = blockIdx.x * blockDim.x + threadIdx.x;
    if (idx >= TOK*DIMC) return;
    int c = idx % DIMC;
    int p = idx / DIMC;
    int xq = p % WW;
    int yq = (p / WW) % HH;
    int n  = p / SEQ;
    float acc = b[c];
    const float* wc = w + c * 9;
    #pragma unroll
    for (int ky = 0; ky < 3; ky++) {
        int yy = yq + ky - 1;
        if (yy < 0 || yy >= HH) continue;
        #pragma unroll
        for (int kx = 0; kx < 3; kx++) {
            int xx = xq + kx - 1;
            if (xx < 0 || xx >= WW) continue;
            acc += wc[ky*3+kx] * xn[((size_t)n*SEQ + yy*WW + xx)*DIMC + c];
        }
    }
    xs[idx] = acc;
}

// ---------------- all 6 weight transposes [K,N]->[N,K] in one kernel -----
struct TransParams {
    const float* in[6];
    float*       out[6];
};
__global__ __launch_bounds__(256) void transpose_all_kernel(TransParams tp)
{
    const int tK[6] = {DIMC, DIMC, DIC, DIC, DIMC, MLPD};
    const int tN[6] = {2*DIC, 2*DIC, DIMC, DIMC, MLPD, DIMC};
    int id = blockIdx.z;
    int K = tK[id], N = tN[id];
    int kb = blockIdx.x * 32, nb = blockIdx.y * 32;
    if (kb >= K || nb >= N) return;
    const float* in = tp.in[id];
    float* out = tp.out[id];
    __shared__ float t[32][33];
    int tx = threadIdx.x & 31, ty = threadIdx.x >> 5;   // 32 x 8
    #pragma unroll
    for (int i = 0; i < 32; i += 8)
        t[ty+i][tx] = in[(size_t)(kb+ty+i)*N + nb+tx];
    __syncthreads();
    #pragma unroll
    for (int i = 0; i < 32; i += 8)
        out[(size_t)(nb+ty+i)*K + kb+tx] = t[tx][ty+i];
}

// ---------------- tf32 tensor GEMM, cp.async 4-stage pipeline ------------
// C[M,N] = act(A[M,K] @ Bt[N,K]^T + bias) + add.  ACT: 0=none, 1=exact GELU.
// CTA: 128 threads, tile 128 x 128, K-tile 16. 4 warps as 2(m) x 2(n);
// warp tile 64 x 64 (Mt=4, Nt=8 m16n8k8 frags). 2 CTAs/SM for overlap.
#define STAGES 4
#define APITCH 80
#define ABYTES (128*APITCH)
#define STB    (2*ABYTES)
#define GSMEM  (STAGES*STB)    // 81920

template<int ACT>
__global__ __launch_bounds__(128) void tc_gemm(
    const float* __restrict__ A, const float* __restrict__ Bt,
    const float* __restrict__ bias, const float* __restrict__ addp,
    float* __restrict__ C, int M, int N, int K)
{
    extern __shared__ char smem[];
    const uint32_t sbase = smem_to_u32(smem);

    const int tid  = threadIdx.x;
    const int wid  = tid >> 5;
    const int lane = tid & 31;
    const int wm   = wid & 1;                // warp m (2)
    const int wn   = wid >> 1;               // warp n (2)
    const int gid  = lane >> 2;              // 0..7
    const int tig  = lane & 3;               // 0..3
    const int m0   = blockIdx.y * 128;
    const int n0   = blockIdx.x * 128;
    const int nk   = K >> 4;

    float acc[4][8][4];
    #pragma unroll
    for (int mi = 0; mi < 4; mi++)
        #pragma unroll
        for (int ni = 0; ni < 8; ni++)
            #pragma unroll
            for (int q = 0; q < 4; q++) acc[mi][ni][q] = 0.f;

    // ---- tile loader: global -> smem stage via cp.async (16B chunks) ----
    auto load_tile = [&](int i) {
        uint32_t sa = sbase + (i % STAGES) * STB;
        uint32_t sb = sa + ABYTES;
        const float* Ag = A  + (size_t)m0 * K + i*16;
        const float* Bg = Bt + (size_t)n0 * K + i*16;
        #pragma unroll
        for (int t = 0; t < 4; t++) {                 // A: 512 chunks
            int f = tid + t*128;
            int r = f >> 2, kc = f & 3;
            CP_ASYNC16(sa + r*APITCH + kc*16, Ag + (size_t)r*K + kc*4);
        }
        #pragma unroll
        for (int t = 0; t < 4; t++) {                 // B: 512 chunks
            int f = tid + t*128;
            int r = f >> 2, kc = f & 3;
            CP_ASYNC16(sb + r*APITCH + kc*16, Bg + (size_t)r*K + kc*4);
        }
    };

    #pragma unroll
    for (int s = 0; s < STAGES-1; s++) { if (s < nk) load_tile(s); CP_COMMIT(); }

    for (int i = 0; i < nk; i++) {
        CP_WAIT(STAGES-2);
        __syncthreads();
        int inext = i + STAGES - 1;
        if (inext < nk) load_tile(inext);
        CP_COMMIT();

        uint32_t sa = sbase + (i % STAGES) * STB;
        uint32_t sb = sa + ABYTES;
        #pragma unroll
        for (int ks = 0; ks < 2; ks++) {
            uint32_t af[4][4];
            #pragma unroll
            for (int mi = 0; mi < 4; mi++) {
                uint32_t ba = sa + (wm*64 + mi*16 + gid)*APITCH + (ks*8+tig)*4;
                af[mi][0] = lds32(ba);
                af[mi][1] = lds32(ba + 8*APITCH);
                af[mi][2] = lds32(ba + 16);
                af[mi][3] = lds32(ba + 8*APITCH + 16);
            }
            uint32_t bf[8][2];
            #pragma unroll
            for (int ni = 0; ni < 8; ni++) {
                uint32_t bb = sb + (wn*64 + ni*8 + gid)*APITCH + (ks*8+tig)*4;
                bf[ni][0] = lds32(bb);
                bf[ni][1] = lds32(bb + 16);
            }
            #pragma unroll
            for (int mi = 0; mi < 4; mi++)
                #pragma unroll
                for (int ni = 0; ni < 8; ni++)
                    MMA_TF32(acc[mi][ni], af[mi][0], af[mi][1], af[mi][2], af[mi][3],
                             bf[ni][0], bf[ni][1]);
        }
        __syncthreads();
    }

    // ---- epilogue: c0=(gid,2tig) c1=(gid,2tig+1) c2/c3 at row+8 ----------
    #pragma unroll
    for (int mi = 0; mi < 4; mi++) {
        int r0 = m0 + wm*64 + mi*16 + gid;
        #pragma unroll
        for (int ni = 0; ni < 8; ni++) {
            int cn = n0 + wn*64 + ni*8 + tig*2;
            #pragma unroll
            for (int half = 0; half < 2; half++) {
                int r = r0 + half*8;
                float v0 = acc[mi][ni][half*2+0];
                float v1 = acc[mi][ni][half*2+1];
                if (bias) { v0 += bias[cn]; v1 += bias[cn+1]; }
                if (ACT == 1) {
                    v0 = 0.5f * v0 * (1.f + erff(v0 * 0.70710678118654752f));
                    v1 = 0.5f * v1 * (1.f + erff(v1 * 0.70710678118654752f));
                }
                if (addp) {
                    float2 ad = *(const float2*)(addp + (size_t)r*N + cn);
                    v0 += ad.x; v1 += ad.y;
                }
                float2 ov; ov.x = v0; ov.y = v1;
                *(float2*)(C + (size_t)r*N + cn) = ov;
            }
        }
    }
}

// ---------------- minGRU scans: forward (dir 0) and backward (dir 1) -----
__device__ __forceinline__ float softplus_fast(float x) {
    float ax = fabsf(x);
    float sp = __logf(1.f + __expf(-ax));
    return (x > 0.f) ? x + sp : sp;
}

__global__ __launch_bounds__(256) void scan_kernel(
    const float* __restrict__ hg, float* __restrict__ e1, float* __restrict__ e2)
{
    int idx = blockIdx.x * blockDim.x + threadIdx.x;   // 0 .. 2*NB*DIC-1
    int dir = idx / (NB*DIC);
    int r   = idx % (NB*DIC);
    int n   = r / DIC;
    int c   = r % DIC;
    float* e = dir ? e2 : e1;
    const int  coff  = dir * 1536 + c;                 // hid col; gate at +768
    const size_t base  = (size_t)n * SEQ * 3072;
    const size_t ebase = (size_t)n * SEQ * DIC;

    float a = 0.f, L = -INFINITY;
    int t0  = dir ? SEQ-1 : 0;
    int dt  = dir ? -1 : 1;
    for (int s = 0; s < SEQ; s++) {
        int t = t0 + s*dt;
        size_t row = base + (size_t)t * 3072;
        float hid  = hg[row + coff];
        float gate = hg[row + coff + 768];
        float lc = -softplus_fast(gate);                              // log coeff
        float lg = (hid >= 0.f) ? __logf(hid + 0.5f) : -softplus_fast(-hid);
        float lv = gate + lc + lg;            // -softplus(-g) = g - softplus(g)
        a += lc;
        float z  = lv - a;
        float mx = fmaxf(L, z);
        float d  = fabsf(L - z);
        L = mx + __logf(1.f + __expf(-d));
        e[ebase + (size_t)t*DIC + c] = __expf(a + L);
    }
}

// ---------------- launch -------------------------------------------------
extern "C" void kernel_launch(void* const* d_in, const int* in_sizes, int n_in,
                              void* d_out, int out_size)
{
    const float* x        = (const float*)d_in[0];
    const float* gamma1   = (const float*)d_in[1];
    const float* beta1    = (const float*)d_in[2];
    const float* dwc_w    = (const float*)d_in[3];
    const float* dwc_b    = (const float*)d_in[4];
    const float* gru1_w   = (const float*)d_in[5];
    const float* gru1_out = (const float*)d_in[6];
    const float* gru2_w   = (const float*)d_in[7];
    const float* gru2_out = (const float*)d_in[8];
    const float* gamma2   = (const float*)d_in[9];
    const float* beta2    = (const float*)d_in[10];
    const float* p1_w     = (const float*)d_in[11];
    const float* p1_b     = (const float*)d_in[12];
    const float* p2_w     = (const float*)d_in[13];
    const float* p2_b     = (const float*)d_in[14];
    float* out = (float*)d_out;

    float *xn, *xs, *hg, *e1, *e2, *y, *yn, *yh;
    float *wT, *o1T, *o2T, *p1T, *p2T;
    cudaGetSymbolAddress((void**)&xn,  g_xn);
    cudaGetSymbolAddress((void**)&xs,  g_xs);
    cudaGetSymbolAddress((void**)&hg,  g_hg);
    cudaGetSymbolAddress((void**)&e1,  g_e1);
    cudaGetSymbolAddress((void**)&e2,  g_e2);
    cudaGetSymbolAddress((void**)&y,   g_y);
    cudaGetSymbolAddress((void**)&yn,  g_yn);
    cudaGetSymbolAddress((void**)&yh,  g_yh);
    cudaGetSymbolAddress((void**)&wT,  g_wT);
    cudaGetSymbolAddress((void**)&o1T, g_o1T);
    cudaGetSymbolAddress((void**)&o2T, g_o2T);
    cudaGetSymbolAddress((void**)&p1T, g_p1T);
    cudaGetSymbolAddress((void**)&p2T, g_p2T);

    cudaFuncSetAttribute(tc_gemm<0>, cudaFuncAttributeMaxDynamicSharedMemorySize, GSMEM);
    cudaFuncSetAttribute(tc_gemm<1>, cudaFuncAttributeMaxDynamicSharedMemorySize, GSMEM);

    // 0. all weight transposes in one launch (K-major B operands)
    {
        TransParams tp;
        tp.in[0] = gru1_w;   tp.out[0] = wT;               // rows 0..1535
        tp.in[1] = gru2_w;   tp.out[1] = wT + (size_t)1536*DIMC;
        tp.in[2] = gru1_out; tp.out[2] = o1T;
        tp.in[3] = gru2_out; tp.out[3] = o2T;
        tp.in[4] = p1_w;     tp.out[4] = p1T;
        tp.in[5] = p2_w;     tp.out[5] = p2T;
        transpose_all_kernel<<<dim3(48, 48, 6), 256>>>(tp);
    }
    // 1. LN1
    ln_kernel<<<(TOK*32 + 255)/256, 256>>>(x, gamma1, beta1, xn, TOK);
    // 2. depthwise conv 3x3
    dwconv_kernel<<<(TOK*DIMC + 255)/256, 256>>>(xn, dwc_w, dwc_b, xs);
    // 3. fused GRU input projections: hg = xs @ [W1|W2]  (N=3072, K=384)
    tc_gemm<0><<<dim3(3072/128, TOK/128), 128, GSMEM>>>(
        xs, wT, nullptr, nullptr, hg, TOK, 3072, DIMC);
    // 4. forward + backward minGRU scans
    scan_kernel<<<(2*NB*DIC)/256, 256>>>(hg, e1, e2);
    // 5/6. output projections + residual: y = e1@W1o + x; y += e2@W2o
    tc_gemm<0><<<dim3(DIMC/128, TOK/128), 128, GSMEM>>>(
        e1, o1T, nullptr, x, y, TOK, DIMC, DIC);
    tc_gemm<0><<<dim3(DIMC/128, TOK/128), 128, GSMEM>>>(
        e2, o2T, nullptr, y, y, TOK, DIMC, DIC);
    // 7. LN2
    ln_kernel<<<(TOK*32 + 255)/256, 256>>>(y, gamma2, beta2, yn, TOK);
    // 8. MLP up + exact GELU
    tc_gemm<1><<<dim3(MLPD/128, TOK/128), 128, GSMEM>>>(
        yn, p1T, p1_b, nullptr, yh, TOK, MLPD, DIMC);
    // 9. MLP down + bias + residual -> out
    tc_gemm<0><<<dim3(DIMC/128, TOK/128), 128, GSMEM>>>(
        yh, p2T, p2_b, y, out, TOK, DIMC, MLPD);
}

// round 8
// speedup vs baseline: 3.3026x; 1.2134x over previous
#include <cuda_runtime.h>
#include <math.h>
#include <stdint.h>

// ---------------- problem constants (fixed by reference) ----------------
#define NB    32
#define HH    32
#define WW    32
#define SEQ   1024          // H*W
#define DIMC  384
#define DIC   768           // 2*DIM
#define MLPD  1536          // 4*DIM
#define TOK   (NB*SEQ)      // 32768 tokens

// ---------------- scratch (device globals; no runtime alloc) ------------
__device__ float g_xn [(size_t)TOK*DIMC];
__device__ float g_xs [(size_t)TOK*DIMC];
__device__ float g_hg [(size_t)TOK*3072];      // [tok][dir*1536 + {hid:0-767, gate:768-1535}]
__device__ float g_e  [(size_t)TOK*1536];      // [tok][dir*768 + c]
__device__ float g_y  [(size_t)TOK*DIMC];
__device__ float g_yn [(size_t)TOK*DIMC];
__device__ float g_yh [(size_t)TOK*MLPD];
// transposed weights (K-major, [N][K]) for the B operand
__device__ float g_wT  [(size_t)3072*DIMC];    // concat(gru1_w^T, gru2_w^T) rows
__device__ float g_oT  [(size_t)DIMC*1536];    // [384][1536]: cols 0-767 o1^T, 768-1535 o2^T
__device__ float g_p1T [(size_t)MLPD*DIMC];    // [1536][384]
__device__ float g_p2T [(size_t)DIMC*MLPD];    // [384][1536]

// ================= small helpers ========================================
__device__ __forceinline__ uint32_t smem_to_u32(const void* p) {
    uint32_t a;
    asm("{ .reg .u64 t; cvta.to.shared.u64 t, %1; cvt.u32.u64 %0, t; }"
        : "=r"(a) : "l"(p));
    return a;
}
__device__ __forceinline__ uint32_t lds32(uint32_t a) {
    uint32_t v;
    asm volatile("ld.shared.b32 %0, [%1];" : "=r"(v) : "r"(a));
    return v;
}
#define CP_ASYNC16(dst, src) \
    asm volatile("cp.async.cg.shared.global [%0], [%1], 16;" \
                 :: "r"(dst), "l"(src) : "memory")
#define CP_COMMIT() asm volatile("cp.async.commit_group;" ::: "memory")
#define CP_WAIT(n)  asm volatile("cp.async.wait_group %0;" :: "n"(n) : "memory")

#define MMA_TF32(d, a0,a1,a2,a3, b0,b1)                                     \
    asm volatile(                                                           \
        "mma.sync.aligned.m16n8k8.row.col.f32.tf32.tf32.f32 "               \
        "{%0,%1,%2,%3}, {%4,%5,%6,%7}, {%8,%9}, {%0,%1,%2,%3};\n"           \
        : "+f"(d[0]), "+f"(d[1]), "+f"(d[2]), "+f"(d[3])                    \
        : "r"(a0), "r"(a1), "r"(a2), "r"(a3), "r"(b0), "r"(b1))

// ---------------- layer norm: one warp per token row ---------------------
__global__ __launch_bounds__(256) void ln_kernel(
    const float* __restrict__ x, const float* __restrict__ gamma,
    const float* __restrict__ beta, float* __restrict__ out, int rows)
{
    int gw   = (blockIdx.x * blockDim.x + threadIdx.x) >> 5;
    int lane = threadIdx.x & 31;
    if (gw >= rows) return;
    const float* xr = x + (size_t)gw * DIMC;
    float s = 0.f, s2 = 0.f;
    #pragma unroll
    for (int i = lane; i < DIMC; i += 32) { float v = xr[i]; s += v; s2 += v*v; }
    #pragma unroll
    for (int o = 16; o; o >>= 1) {
        s  += __shfl_xor_sync(0xffffffffu, s,  o);
        s2 += __shfl_xor_sync(0xffffffffu, s2, o);
    }
    float mu  = s * (1.f/DIMC);
    float var = s2 * (1.f/DIMC) - mu*mu;
    float inv = rsqrtf(var + 1e-5f);
    float* orow = out + (size_t)gw * DIMC;
    #pragma unroll
    for (int i = lane; i < DIMC; i += 32)
        orow[i] = (xr[i] - mu) * inv * gamma[i] + beta[i];
}

// ---------------- depthwise 3x3 conv, NHWC, pad=1 ------------------------
__global__ __launch_bounds__(256) void dwconv_kernel(
    const float* __restrict__ xn, const float* __restrict__ w,
    const float* __restrict__ b, float* __restrict__ xs)
{
    int idx = blockIdx.x * blockDim.x + threadIdx.x;
    if (idx >= TOK*DIMC) return;
    int c = idx % DIMC;
    int p = idx / DIMC;
    int xq = p % WW;
    int yq = (p / WW) % HH;
    int n  = p / SEQ;
    float acc = b[c];
    const float* wc = w + c * 9;
    #pragma unroll
    for (int ky = 0; ky < 3; ky++) {
        int yy = yq + ky - 1;
        if (yy < 0 || yy >= HH) continue;
        #pragma unroll
        for (int kx = 0; kx < 3; kx++) {
            int xx = xq + kx - 1;
            if (xx < 0 || xx >= WW) continue;
            acc += wc[ky*3+kx] * xn[((size_t)n*SEQ + yy*WW + xx)*DIMC + c];
        }
    }
    xs[idx] = acc;
}

// ---------------- all 6 weight transposes [K,N]->[N,K(stride)] -----------
struct TransParams {
    const float* in[6];
    float*       out[6];
    int K[6], N[6], ostr[6];
};
__global__ __launch_bounds__(256) void transpose_all_kernel(TransParams tp)
{
    int id = blockIdx.z;
    int K = tp.K[id], N = tp.N[id], ostr = tp.ostr[id];
    int kb = blockIdx.x * 32, nb = blockIdx.y * 32;
    if (kb >= K || nb >= N) return;
    const float* in = tp.in[id];
    float* out = tp.out[id];
    __shared__ float t[32][33];
    int tx = threadIdx.x & 31, ty = threadIdx.x >> 5;   // 32 x 8
    #pragma unroll
    for (int i = 0; i < 32; i += 8)
        t[ty+i][tx] = in[(size_t)(kb+ty+i)*N + nb+tx];
    __syncthreads();
    #pragma unroll
    for (int i = 0; i < 32; i += 8)
        out[(size_t)(nb+ty+i)*ostr + kb+tx] = t[tx][ty+i];
}

// ---------------- tf32 tensor GEMM, K-tile 32, 3-stage, reg ping-pong ----
// C[M,N] = act(A[M,K] @ Bt[N,K]^T + bias) + add.  ACT: 0=none, 1=exact GELU.
// CTA: 128 threads, tile 128 x 128. 4 warps as 2(m) x 2(n); warp tile 64x64.
#define STAGES 3
#define APITCH 144                 // 32 floats (128B) + 16B pad
#define ABYTES (128*APITCH)
#define STB    (2*ABYTES)
#define GSMEM  (STAGES*STB)        // 110592

template<int ACT>
__global__ __launch_bounds__(128) void tc_gemm(
    const float* __restrict__ A, const float* __restrict__ Bt,
    const float* __restrict__ bias, const float* __restrict__ addp,
    float* __restrict__ C, int M, int N, int K)
{
    extern __shared__ char smem[];
    const uint32_t sbase = smem_to_u32(smem);

    const int tid  = threadIdx.x;
    const int wid  = tid >> 5;
    const int lane = tid & 31;
    const int wm   = wid & 1;                // warp m (2)
    const int wn   = wid >> 1;               // warp n (2)
    const int gid  = lane >> 2;              // 0..7
    const int tig  = lane & 3;               // 0..3
    const int m0   = blockIdx.y * 128;
    const int n0   = blockIdx.x * 128;
    const int nk   = K >> 5;

    float acc[4][8][4];
    #pragma unroll
    for (int mi = 0; mi < 4; mi++)
        #pragma unroll
        for (int ni = 0; ni < 8; ni++)
            #pragma unroll
            for (int q = 0; q < 4; q++) acc[mi][ni][q] = 0.f;

    // ---- tile loader: global -> smem stage via cp.async (16B chunks) ----
    auto load_tile = [&](int i) {
        uint32_t sa = sbase + (i % STAGES) * STB;
        uint32_t sb = sa + ABYTES;
        const float* Ag = A  + (size_t)m0 * K + i*32;
        const float* Bg = Bt + (size_t)n0 * K + i*32;
        #pragma unroll
        for (int t = 0; t < 8; t++) {                 // A: 1024 chunks
            int f = tid + t*128;
            int r = f >> 3, kc = f & 7;
            CP_ASYNC16(sa + r*APITCH + kc*16, Ag + (size_t)r*K + kc*4);
        }
        #pragma unroll
        for (int t = 0; t < 8; t++) {                 // B: 1024 chunks
            int f = tid + t*128;
            int r = f >> 3, kc = f & 7;
            CP_ASYNC16(sb + r*APITCH + kc*16, Bg + (size_t)r*K + kc*4);
        }
    };

    load_tile(0); CP_COMMIT();
    load_tile(1); CP_COMMIT();

    uint32_t af[2][4][4];
    uint32_t bf[2][8][2];

    for (int i = 0; i < nk; i++) {
        CP_WAIT(1);
        __syncthreads();
        if (i + 2 < nk) load_tile(i + 2);
        CP_COMMIT();

        uint32_t sa = sbase + (i % STAGES) * STB;
        uint32_t sb = sa + ABYTES;
        const uint32_t abase = sa + (wm*64 + gid)*APITCH + tig*4;
        const uint32_t bbase = sb + (wn*64 + gid)*APITCH + tig*4;

        // prefetch ks=0 fragments into buffer 0
        #pragma unroll
        for (int mi = 0; mi < 4; mi++) {
            uint32_t ba = abase + mi*16*APITCH;
            af[0][mi][0] = lds32(ba);
            af[0][mi][1] = lds32(ba + 8*APITCH);
            af[0][mi][2] = lds32(ba + 16);
            af[0][mi][3] = lds32(ba + 8*APITCH + 16);
        }
        #pragma unroll
        for (int ni = 0; ni < 8; ni++) {
            uint32_t bb = bbase + ni*8*APITCH;
            bf[0][ni][0] = lds32(bb);
            bf[0][ni][1] = lds32(bb + 16);
        }

        #pragma unroll
        for (int ks = 0; ks < 4; ks++) {
            int cur = ks & 1, nxt = cur ^ 1;
            if (ks < 3) {
                uint32_t ko = (ks+1)*32;   // bytes: 8 k-floats per step
                #pragma unroll
                for (int mi = 0; mi < 4; mi++) {
                    uint32_t ba = abase + mi*16*APITCH + ko;
                    af[nxt][mi][0] = lds32(ba);
                    af[nxt][mi][1] = lds32(ba + 8*APITCH);
                    af[nxt][mi][2] = lds32(ba + 16);
                    af[nxt][mi][3] = lds32(ba + 8*APITCH + 16);
                }
                #pragma unroll
                for (int ni = 0; ni < 8; ni++) {
                    uint32_t bb = bbase + ni*8*APITCH + ko;
                    bf[nxt][ni][0] = lds32(bb);
                    bf[nxt][ni][1] = lds32(bb + 16);
                }
            }
            #pragma unroll
            for (int mi = 0; mi < 4; mi++)
                #pragma unroll
                for (int ni = 0; ni < 8; ni++)
                    MMA_TF32(acc[mi][ni],
                             af[cur][mi][0], af[cur][mi][1], af[cur][mi][2], af[cur][mi][3],
                             bf[cur][ni][0], bf[cur][ni][1]);
        }
    }

    // ---- epilogue: c0=(gid,2tig) c1=(gid,2tig+1) c2/c3 at row+8 ----------
    #pragma unroll
    for (int mi = 0; mi < 4; mi++) {
        int r0 = m0 + wm*64 + mi*16 + gid;
        #pragma unroll
        for (int ni = 0; ni < 8; ni++) {
            int cn = n0 + wn*64 + ni*8 + tig*2;
            #pragma unroll
            for (int half = 0; half < 2; half++) {
                int r = r0 + half*8;
                float v0 = acc[mi][ni][half*2+0];
                float v1 = acc[mi][ni][half*2+1];
                if (bias) { v0 += bias[cn]; v1 += bias[cn+1]; }
                if (ACT == 1) {
                    v0 = 0.5f * v0 * (1.f + erff(v0 * 0.70710678118654752f));
                    v1 = 0.5f * v1 * (1.f + erff(v1 * 0.70710678118654752f));
                }
                if (addp) {
                    float2 ad = *(const float2*)(addp + (size_t)r*N + cn);
                    v0 += ad.x; v1 += ad.y;
                }
                float2 ov; ov.x = v0; ov.y = v1;
                *(float2*)(C + (size_t)r*N + cn) = ov;
            }
        }
    }
}

// ---------------- minGRU scans: forward (dir 0) and backward (dir 1) -----
__device__ __forceinline__ float softplus_fast(float x) {
    float ax = fabsf(x);
    float sp = __logf(1.f + __expf(-ax));
    return (x > 0.f) ? x + sp : sp;
}

__global__ __launch_bounds__(256) void scan_kernel(
    const float* __restrict__ hg, float* __restrict__ e)
{
    int idx = blockIdx.x * blockDim.x + threadIdx.x;   // 0 .. 2*NB*DIC-1
    int dir = idx / (NB*DIC);
    int r   = idx % (NB*DIC);
    int n   = r / DIC;
    int c   = r % DIC;
    const int coff  = dir * 1536 + c;                  // hid col; gate at +768
    const int eoff  = dir * 768 + c;
    const size_t base  = (size_t)n * SEQ * 3072;
    const size_t ebase = (size_t)n * SEQ * 1536;

    float a = 0.f, L = -INFINITY;
    int t0  = dir ? SEQ-1 : 0;
    int dt  = dir ? -1 : 1;
    for (int s = 0; s < SEQ; s++) {
        int t = t0 + s*dt;
        size_t row = base + (size_t)t * 3072;
        float hid  = hg[row + coff];
        float gate = hg[row + coff + 768];
        float lc = -softplus_fast(gate);                              // log coeff
        float lg = (hid >= 0.f) ? __logf(hid + 0.5f) : -softplus_fast(-hid);
        float lv = gate + lc + lg;            // -softplus(-g) = g - softplus(g)
        a += lc;
        float z  = lv - a;
        float mx = fmaxf(L, z);
        float d  = fabsf(L - z);
        L = mx + __logf(1.f + __expf(-d));
        e[ebase + (size_t)t*1536 + eoff] = __expf(a + L);
    }
}

// ---------------- launch -------------------------------------------------
extern "C" void kernel_launch(void* const* d_in, const int* in_sizes, int n_in,
                              void* d_out, int out_size)
{
    const float* x        = (const float*)d_in[0];
    const float* gamma1   = (const float*)d_in[1];
    const float* beta1    = (const float*)d_in[2];
    const float* dwc_w    = (const float*)d_in[3];
    const float* dwc_b    = (const float*)d_in[4];
    const float* gru1_w   = (const float*)d_in[5];
    const float* gru1_out = (const float*)d_in[6];
    const float* gru2_w   = (const float*)d_in[7];
    const float* gru2_out = (const float*)d_in[8];
    const float* gamma2   = (const float*)d_in[9];
    const float* beta2    = (const float*)d_in[10];
    const float* p1_w     = (const float*)d_in[11];
    const float* p1_b     = (const float*)d_in[12];
    const float* p2_w     = (const float*)d_in[13];
    const float* p2_b     = (const float*)d_in[14];
    float* out = (float*)d_out;

    float *xn, *xs, *hg, *e, *y, *yn, *yh;
    float *wT, *oT, *p1T, *p2T;
    cudaGetSymbolAddress((void**)&xn,  g_xn);
    cudaGetSymbolAddress((void**)&xs,  g_xs);
    cudaGetSymbolAddress((void**)&hg,  g_hg);
    cudaGetSymbolAddress((void**)&e,   g_e);
    cudaGetSymbolAddress((void**)&y,   g_y);
    cudaGetSymbolAddress((void**)&yn,  g_yn);
    cudaGetSymbolAddress((void**)&yh,  g_yh);
    cudaGetSymbolAddress((void**)&wT,  g_wT);
    cudaGetSymbolAddress((void**)&oT,  g_oT);
    cudaGetSymbolAddress((void**)&p1T, g_p1T);
    cudaGetSymbolAddress((void**)&p2T, g_p2T);

    cudaFuncSetAttribute(tc_gemm<0>, cudaFuncAttributeMaxDynamicSharedMemorySize, GSMEM);
    cudaFuncSetAttribute(tc_gemm<1>, cudaFuncAttributeMaxDynamicSharedMemorySize, GSMEM);

    // 0. all weight transposes in one launch (K-major B operands)
    {
        TransParams tp;
        // fused GRU input weights: [3072][384]
        tp.in[0]=gru1_w;   tp.out[0]=wT;                      tp.K[0]=DIMC; tp.N[0]=2*DIC; tp.ostr[0]=DIMC;
        tp.in[1]=gru2_w;   tp.out[1]=wT+(size_t)1536*DIMC;    tp.K[1]=DIMC; tp.N[1]=2*DIC; tp.ostr[1]=DIMC;
        // fused output-proj weights: [384][1536], o1 cols 0-767, o2 cols 768-1535
        tp.in[2]=gru1_out; tp.out[2]=oT;                      tp.K[2]=DIC;  tp.N[2]=DIMC;  tp.ostr[2]=1536;
        tp.in[3]=gru2_out; tp.out[3]=oT+768;                  tp.K[3]=DIC;  tp.N[3]=DIMC;  tp.ostr[3]=1536;
        tp.in[4]=p1_w;     tp.out[4]=p1T;                     tp.K[4]=DIMC; tp.N[4]=MLPD;  tp.ostr[4]=DIMC;
        tp.in[5]=p2_w;     tp.out[5]=p2T;                     tp.K[5]=MLPD; tp.N[5]=DIMC;  tp.ostr[5]=MLPD;
        transpose_all_kernel<<<dim3(48, 48, 6), 256>>>(tp);
    }
    // 1. LN1
    ln_kernel<<<(TOK*32 + 255)/256, 256>>>(x, gamma1, beta1, xn, TOK);
    // 2. depthwise conv 3x3
    dwconv_kernel<<<(TOK*DIMC + 255)/256, 256>>>(xn, dwc_w, dwc_b, xs);
    // 3. fused GRU input projections: hg = xs @ [W1|W2]  (N=3072, K=384)
    tc_gemm<0><<<dim3(3072/128, TOK/128), 128, GSMEM>>>(
        xs, wT, nullptr, nullptr, hg, TOK, 3072, DIMC);
    // 4. forward + backward minGRU scans -> e[tok][1536]
    scan_kernel<<<(2*NB*DIC)/256, 256>>>(hg, e);
    // 5. fused output projections + residual: y = e @ [O1;O2] + x  (K=1536)
    tc_gemm<0><<<dim3(DIMC/128, TOK/128), 128, GSMEM>>>(
        e, oT, nullptr, x, y, TOK, DIMC, 1536);
    // 6. LN2
    ln_kernel<<<(TOK*32 + 255)/256, 256>>>(y, gamma2, beta2, yn, TOK);
    // 7. MLP up + exact GELU
    tc_gemm<1><<<dim3(MLPD/128, TOK/128), 128, GSMEM>>>(
        yn, p1T, p1_b, nullptr, yh, TOK, MLPD, DIMC);
    // 8. MLP down + bias + residual -> out
    tc_gemm<0><<<dim3(DIMC/128, TOK/128), 128, GSMEM>>>(
        yh, p2T, p2_b, y, out, TOK, DIMC, MLPD);
}

// round 9
// speedup vs baseline: 4.7173x; 1.4284x over previous
#include <cuda_runtime.h>
#include <cuda_fp16.h>
#include <math.h>
#include <stdint.h>

// ---------------- problem constants (fixed by reference) ----------------
#define NB    32
#define HH    32
#define WW    32
#define SEQ   1024          // H*W
#define DIMC  384
#define DIC   768           // 2*DIM
#define MLPD  1536          // 4*DIM
#define TOK   (NB*SEQ)      // 32768 tokens

// ---------------- scratch (device globals; no runtime alloc) ------------
__device__ float g_xn [(size_t)TOK*DIMC];
__device__ __align__(16) __half g_xs [(size_t)TOK*DIMC];
__device__ float g_hg [(size_t)TOK*3072];      // [tok][dir*1536 + {hid,gate}]
__device__ __align__(16) __half g_e  [(size_t)TOK*1536];      // [tok][dir*768 + c]
__device__ float g_y  [(size_t)TOK*DIMC];
__device__ __align__(16) __half g_yn [(size_t)TOK*DIMC];
__device__ __align__(16) __half g_yh [(size_t)TOK*MLPD];
// transposed weights (K-major, [N][K]) for the B operand, fp16
__device__ __align__(16) __half g_wT  [(size_t)3072*DIMC];
__device__ __align__(16) __half g_oT  [(size_t)DIMC*1536];    // cols 0-767 o1^T, 768-1535 o2^T
__device__ __align__(16) __half g_p1T [(size_t)MLPD*DIMC];
__device__ __align__(16) __half g_p2T [(size_t)DIMC*MLPD];

// ================= small helpers ========================================
__device__ __forceinline__ uint32_t smem_to_u32(const void* p) {
    uint32_t a;
    asm("{ .reg .u64 t; cvta.to.shared.u64 t, %1; cvt.u32.u64 %0, t; }"
        : "=r"(a) : "l"(p));
    return a;
}
__device__ __forceinline__ uint32_t lds32(uint32_t a) {
    uint32_t v;
    asm volatile("ld.shared.b32 %0, [%1];" : "=r"(v) : "r"(a));
    return v;
}
#define CP_ASYNC16(dst, src) \
    asm volatile("cp.async.cg.shared.global [%0], [%1], 16;" \
                 :: "r"(dst), "l"(src) : "memory")
#define CP_COMMIT() asm volatile("cp.async.commit_group;" ::: "memory")
#define CP_WAIT(n)  asm volatile("cp.async.wait_group %0;" :: "n"(n) : "memory")

#define MMA_F16(d, a0,a1,a2,a3, b0,b1)                                      \
    asm volatile(                                                           \
        "mma.sync.aligned.m16n8k16.row.col.f32.f16.f16.f32 "                \
        "{%0,%1,%2,%3}, {%4,%5,%6,%7}, {%8,%9}, {%0,%1,%2,%3};\n"           \
        : "+f"(d[0]), "+f"(d[1]), "+f"(d[2]), "+f"(d[3])                    \
        : "r"(a0), "r"(a1), "r"(a2), "r"(a3), "r"(b0), "r"(b1))

// ---------------- layer norm: one warp per token row ---------------------
template<typename OT>
__global__ __launch_bounds__(256) void ln_kernel(
    const float* __restrict__ x, const float* __restrict__ gamma,
    const float* __restrict__ beta, OT* __restrict__ out, int rows)
{
    int gw   = (blockIdx.x * blockDim.x + threadIdx.x) >> 5;
    int lane = threadIdx.x & 31;
    if (gw >= rows) return;
    const float* xr = x + (size_t)gw * DIMC;
    float s = 0.f, s2 = 0.f;
    #pragma unroll
    for (int i = lane; i < DIMC; i += 32) { float v = xr[i]; s += v; s2 += v*v; }
    #pragma unroll
    for (int o = 16; o; o >>= 1) {
        s  += __shfl_xor_sync(0xffffffffu, s,  o);
        s2 += __shfl_xor_sync(0xffffffffu, s2, o);
    }
    float mu  = s * (1.f/DIMC);
    float var = s2 * (1.f/DIMC) - mu*mu;
    float inv = rsqrtf(var + 1e-5f);
    OT* orow = out + (size_t)gw * DIMC;
    #pragma unroll
    for (int i = lane; i < DIMC; i += 32)
        orow[i] = (OT)((xr[i] - mu) * inv * gamma[i] + beta[i]);
}

// ---------------- depthwise 3x3 conv, NHWC, pad=1; fp16 output ----------
__global__ __launch_bounds__(256) void dwconv_kernel(
    const float* __restrict__ xn, const float* __restrict__ w,
    const float* __restrict__ b, __half* __restrict__ xs)
{
    int idx = blockIdx.x * blockDim.x + threadIdx.x;
    if (idx >= TOK*DIMC) return;
    int c = idx % DIMC;
    int p = idx / DIMC;
    int xq = p % WW;
    int yq = (p / WW) % HH;
    int n  = p / SEQ;
    float acc = b[c];
    const float* wc = w + c * 9;
    #pragma unroll
    for (int ky = 0; ky < 3; ky++) {
        int yy = yq + ky - 1;
        if (yy < 0 || yy >= HH) continue;
        #pragma unroll
        for (int kx = 0; kx < 3; kx++) {
            int xx = xq + kx - 1;
            if (xx < 0 || xx >= WW) continue;
            acc += wc[ky*3+kx] * xn[((size_t)n*SEQ + yy*WW + xx)*DIMC + c];
        }
    }
    xs[idx] = __float2half(acc);
}

// ---------------- all 6 weight transposes [K,N]->fp16 [N,K(stride)] ------
struct TransParams {
    const float* in[6];
    __half*      out[6];
    int K[6], N[6], ostr[6];
};
__global__ __launch_bounds__(256) void transpose_all_kernel(TransParams tp)
{
    int id = blockIdx.z;
    int K = tp.K[id], N = tp.N[id], ostr = tp.ostr[id];
    int kb = blockIdx.x * 32, nb = blockIdx.y * 32;
    if (kb >= K || nb >= N) return;
    const float* in = tp.in[id];
    __half* out = tp.out[id];
    __shared__ float t[32][33];
    int tx = threadIdx.x & 31, ty = threadIdx.x >> 5;   // 32 x 8
    #pragma unroll
    for (int i = 0; i < 32; i += 8)
        t[ty+i][tx] = in[(size_t)(kb+ty+i)*N + nb+tx];
    __syncthreads();
    #pragma unroll
    for (int i = 0; i < 32; i += 8)
        out[(size_t)(nb+ty+i)*ostr + kb+tx] = __float2half(t[tx][ty+i]);
}

// ---------------- fp16 tensor GEMM, K-tile 64, 3-stage, reg ping-pong ----
// C[M,N] = act(A[M,K] @ Bt[N,K]^T + bias) + add.  ACT: 0=none, 1=exact GELU.
// CTA: 128 threads, tile 128 x 128. 4 warps as 2(m) x 2(n); warp tile 64x64.
// m16n8k16 f16->f32; per tile 4 k16 steps with register ping-pong.
#define STAGES 3
#define APITCH 144                 // 64 halves (128B) + 16B pad
#define ABYTES (128*APITCH)
#define STB    (2*ABYTES)
#define GSMEM  (STAGES*STB)        // 110592

template<int ACT, typename CT>
__global__ __launch_bounds__(128) void tc_gemm(
    const __half* __restrict__ A, const __half* __restrict__ Bt,
    const float* __restrict__ bias, const float* __restrict__ addp,
    CT* __restrict__ C, int M, int N, int K)
{
    extern __shared__ char smem[];
    const uint32_t sbase = smem_to_u32(smem);

    const int tid  = threadIdx.x;
    const int wid  = tid >> 5;
    const int lane = tid & 31;
    const int wm   = wid & 1;                // warp m (2)
    const int wn   = wid >> 1;               // warp n (2)
    const int gid  = lane >> 2;              // 0..7
    const int tig  = lane & 3;               // 0..3
    const int m0   = blockIdx.y * 128;
    const int n0   = blockIdx.x * 128;
    const int nk   = K >> 6;                 // 64-k tiles

    float acc[4][8][4];
    #pragma unroll
    for (int mi = 0; mi < 4; mi++)
        #pragma unroll
        for (int ni = 0; ni < 8; ni++)
            #pragma unroll
            for (int q = 0; q < 4; q++) acc[mi][ni][q] = 0.f;

    // ---- tile loader: global -> smem stage via cp.async (16B = 8 halves) --
    auto load_tile = [&](int i) {
        uint32_t sa = sbase + (i % STAGES) * STB;
        uint32_t sb = sa + ABYTES;
        const __half* Ag = A  + (size_t)m0 * K + i*64;
        const __half* Bg = Bt + (size_t)n0 * K + i*64;
        #pragma unroll
        for (int t = 0; t < 8; t++) {                 // A: 1024 chunks
            int f = tid + t*128;
            int r = f >> 3, kc = f & 7;
            CP_ASYNC16(sa + r*APITCH + kc*16, Ag + (size_t)r*K + kc*8);
        }
        #pragma unroll
        for (int t = 0; t < 8; t++) {                 // B: 1024 chunks
            int f = tid + t*128;
            int r = f >> 3, kc = f & 7;
            CP_ASYNC16(sb + r*APITCH + kc*16, Bg + (size_t)r*K + kc*8);
        }
    };

    load_tile(0); CP_COMMIT();
    load_tile(1); CP_COMMIT();

    uint32_t af[2][4][4];
    uint32_t bf[2][8][2];

    for (int i = 0; i < nk; i++) {
        CP_WAIT(1);
        __syncthreads();
        if (i + 2 < nk) load_tile(i + 2);
        CP_COMMIT();

        uint32_t sa = sbase + (i % STAGES) * STB;
        uint32_t sb = sa + ABYTES;
        const uint32_t abase = sa + (wm*64 + gid)*APITCH + tig*4;
        const uint32_t bbase = sb + (wn*64 + gid)*APITCH + tig*4;

        // prefetch ks=0 fragments into buffer 0
        #pragma unroll
        for (int mi = 0; mi < 4; mi++) {
            uint32_t ba = abase + mi*16*APITCH;
            af[0][mi][0] = lds32(ba);                  // (gid,      2tig)
            af[0][mi][1] = lds32(ba + 8*APITCH);       // (gid+8,    2tig)
            af[0][mi][2] = lds32(ba + 16);             // (gid,      2tig+8)
            af[0][mi][3] = lds32(ba + 8*APITCH + 16);  // (gid+8,    2tig+8)
        }
        #pragma unroll
        for (int ni = 0; ni < 8; ni++) {
            uint32_t bb = bbase + ni*8*APITCH;
            bf[0][ni][0] = lds32(bb);                  // (2tig,   n=gid)
            bf[0][ni][1] = lds32(bb + 16);             // (2tig+8, n=gid)
        }

        #pragma unroll
        for (int ks = 0; ks < 4; ks++) {
            int cur = ks & 1, nxt = cur ^ 1;
            if (ks < 3) {
                uint32_t ko = (ks+1)*32;   // 16 halves = 32 bytes per k16 step
                #pragma unroll
                for (int mi = 0; mi < 4; mi++) {
                    uint32_t ba = abase + mi*16*APITCH + ko;
                    af[nxt][mi][0] = lds32(ba);
                    af[nxt][mi][1] = lds32(ba + 8*APITCH);
                    af[nxt][mi][2] = lds32(ba + 16);
                    af[nxt][mi][3] = lds32(ba + 8*APITCH + 16);
                }
                #pragma unroll
                for (int ni = 0; ni < 8; ni++) {
                    uint32_t bb = bbase + ni*8*APITCH + ko;
                    bf[nxt][ni][0] = lds32(bb);
                    bf[nxt][ni][1] = lds32(bb + 16);
                }
            }
            #pragma unroll
            for (int mi = 0; mi < 4; mi++)
                #pragma unroll
                for (int ni = 0; ni < 8; ni++)
                    MMA_F16(acc[mi][ni],
                            af[cur][mi][0], af[cur][mi][1], af[cur][mi][2], af[cur][mi][3],
                            bf[cur][ni][0], bf[cur][ni][1]);
        }
    }

    // ---- epilogue: c0=(gid,2tig) c1=(gid,2tig+1) c2/c3 at row+8 ----------
    #pragma unroll
    for (int mi = 0; mi < 4; mi++) {
        int r0 = m0 + wm*64 + mi*16 + gid;
        #pragma unroll
        for (int ni = 0; ni < 8; ni++) {
            int cn = n0 + wn*64 + ni*8 + tig*2;
            #pragma unroll
            for (int half = 0; half < 2; half++) {
                int r = r0 + half*8;
                float v0 = acc[mi][ni][half*2+0];
                float v1 = acc[mi][ni][half*2+1];
                if (bias) { v0 += bias[cn]; v1 += bias[cn+1]; }
                if (ACT == 1) {
                    v0 = 0.5f * v0 * (1.f + erff(v0 * 0.70710678118654752f));
                    v1 = 0.5f * v1 * (1.f + erff(v1 * 0.70710678118654752f));
                }
                if (addp) {
                    float2 ad = *(const float2*)(addp + (size_t)r*N + cn);
                    v0 += ad.x; v1 += ad.y;
                }
                if (sizeof(CT) == 2) {
                    __half2 hv = __floats2half2_rn(v0, v1);
                    *(__half2*)((__half*)C + (size_t)r*N + cn) = hv;
                } else {
                    float2 ov; ov.x = v0; ov.y = v1;
                    *(float2*)((float*)C + (size_t)r*N + cn) = ov;
                }
            }
        }
    }
}

// ---------------- minGRU scans: forward (dir 0) and backward (dir 1) -----
__device__ __forceinline__ float softplus_fast(float x) {
    float ax = fabsf(x);
    float sp = __logf(1.f + __expf(-ax));
    return (x > 0.f) ? x + sp : sp;
}

__global__ __launch_bounds__(256) void scan_kernel(
    const float* __restrict__ hg, __half* __restrict__ e)
{
    int idx = blockIdx.x * blockDim.x + threadIdx.x;   // 0 .. 2*NB*DIC-1
    int dir = idx / (NB*DIC);
    int r   = idx % (NB*DIC);
    int n   = r / DIC;
    int c   = r % DIC;
    const int coff  = dir * 1536 + c;                  // hid col; gate at +768
    const int eoff  = dir * 768 + c;
    const size_t base  = (size_t)n * SEQ * 3072;
    const size_t ebase = (size_t)n * SEQ * 1536;

    float a = 0.f, L = -INFINITY;
    int t0  = dir ? SEQ-1 : 0;
    int dt  = dir ? -1 : 1;
    for (int s = 0; s < SEQ; s++) {
        int t = t0 + s*dt;
        size_t row = base + (size_t)t * 3072;
        float hid  = hg[row + coff];
        float gate = hg[row + coff + 768];
        float lc = -softplus_fast(gate);                              // log coeff
        float lg = (hid >= 0.f) ? __logf(hid + 0.5f) : -softplus_fast(-hid);
        float lv = gate + lc + lg;            // -softplus(-g) = g - softplus(g)
        a += lc;
        float z  = lv - a;
        float mx = fmaxf(L, z);
        float d  = fabsf(L - z);
        L = mx + __logf(1.f + __expf(-d));
        e[ebase + (size_t)t*1536 + eoff] = __float2half(__expf(a + L));
    }
}

// ---------------- launch -------------------------------------------------
extern "C" void kernel_launch(void* const* d_in, const int* in_sizes, int n_in,
                              void* d_out, int out_size)
{
    const float* x        = (const float*)d_in[0];
    const float* gamma1   = (const float*)d_in[1];
    const float* beta1    = (const float*)d_in[2];
    const float* dwc_w    = (const float*)d_in[3];
    const float* dwc_b    = (const float*)d_in[4];
    const float* gru1_w   = (const float*)d_in[5];
    const float* gru1_out = (const float*)d_in[6];
    const float* gru2_w   = (const float*)d_in[7];
    const float* gru2_out = (const float*)d_in[8];
    const float* gamma2   = (const float*)d_in[9];
    const float* beta2    = (const float*)d_in[10];
    const float* p1_w     = (const float*)d_in[11];
    const float* p1_b     = (const float*)d_in[12];
    const float* p2_w     = (const float*)d_in[13];
    const float* p2_b     = (const float*)d_in[14];
    float* out = (float*)d_out;

    float *xn, *hg, *y;
    __half *xs, *e, *yn, *yh, *wT, *oT, *p1T, *p2T;
    cudaGetSymbolAddress((void**)&xn,  g_xn);
    cudaGetSymbolAddress((void**)&xs,  g_xs);
    cudaGetSymbolAddress((void**)&hg,  g_hg);
    cudaGetSymbolAddress((void**)&e,   g_e);
    cudaGetSymbolAddress((void**)&y,   g_y);
    cudaGetSymbolAddress((void**)&yn,  g_yn);
    cudaGetSymbolAddress((void**)&yh,  g_yh);
    cudaGetSymbolAddress((void**)&wT,  g_wT);
    cudaGetSymbolAddress((void**)&oT,  g_oT);
    cudaGetSymbolAddress((void**)&p1T, g_p1T);
    cudaGetSymbolAddress((void**)&p2T, g_p2T);

    cudaFuncSetAttribute(tc_gemm<0,float>,  cudaFuncAttributeMaxDynamicSharedMemorySize, GSMEM);
    cudaFuncSetAttribute(tc_gemm<1,__half>, cudaFuncAttributeMaxDynamicSharedMemorySize, GSMEM);

    // 0. all weight transposes in one launch (K-major fp16 B operands)
    {
        TransParams tp;
        // fused GRU input weights: [3072][384]
        tp.in[0]=gru1_w;   tp.out[0]=wT;                      tp.K[0]=DIMC; tp.N[0]=2*DIC; tp.ostr[0]=DIMC;
        tp.in[1]=gru2_w;   tp.out[1]=wT+(size_t)1536*DIMC;    tp.K[1]=DIMC; tp.N[1]=2*DIC; tp.ostr[1]=DIMC;
        // fused output-proj weights: [384][1536]
        tp.in[2]=gru1_out; tp.out[2]=oT;                      tp.K[2]=DIC;  tp.N[2]=DIMC;  tp.ostr[2]=1536;
        tp.in[3]=gru2_out; tp.out[3]=oT+768;                  tp.K[3]=DIC;  tp.N[3]=DIMC;  tp.ostr[3]=1536;
        tp.in[4]=p1_w;     tp.out[4]=p1T;                     tp.K[4]=DIMC; tp.N[4]=MLPD;  tp.ostr[4]=DIMC;
        tp.in[5]=p2_w;     tp.out[5]=p2T;                     tp.K[5]=MLPD; tp.N[5]=DIMC;  tp.ostr[5]=MLPD;
        transpose_all_kernel<<<dim3(48, 48, 6), 256>>>(tp);
    }
    // 1. LN1 (f32 out -> conv input)
    ln_kernel<float><<<(TOK*32 + 255)/256, 256>>>(x, gamma1, beta1, xn, TOK);
    // 2. depthwise conv 3x3 (fp16 out)
    dwconv_kernel<<<(TOK*DIMC + 255)/256, 256>>>(xn, dwc_w, dwc_b, xs);
    // 3. fused GRU input projections: hg = xs @ [W1|W2]  (N=3072, K=384), f32 out
    tc_gemm<0,float><<<dim3(3072/128, TOK/128), 128, GSMEM>>>(
        xs, wT, nullptr, nullptr, hg, TOK, 3072, DIMC);
    // 4. forward + backward minGRU scans -> e[tok][1536] fp16
    scan_kernel<<<(2*NB*DIC)/256, 256>>>(hg, e);
    // 5. fused output projections + residual: y = e @ [O1;O2] + x  (K=1536), f32
    tc_gemm<0,float><<<dim3(DIMC/128, TOK/128), 128, GSMEM>>>(
        e, oT, nullptr, x, y, TOK, DIMC, 1536);
    // 6. LN2 (fp16 out)
    ln_kernel<__half><<<(TOK*32 + 255)/256, 256>>>(y, gamma2, beta2, yn, TOK);
    // 7. MLP up + exact GELU (fp16 out)
    tc_gemm<1,__half><<<dim3(MLPD/128, TOK/128), 128, GSMEM>>>(
        yn, p1T, p1_b, nullptr, yh, TOK, MLPD, DIMC);
    // 8. MLP down + bias + residual -> out (f32)
    tc_gemm<0,float><<<dim3(DIMC/128, TOK/128), 128, GSMEM>>>(
        yh, p2T, p2_b, y, out, TOK, DIMC, MLPD);
}

// round 10
// speedup vs baseline: 5.5116x; 1.1684x over previous
#include <cuda_runtime.h>
#include <cuda_fp16.h>
#include <math.h>
#include <stdint.h>

// ---------------- problem constants (fixed by reference) ----------------
#define NB    32
#define HH    32
#define WW    32
#define SEQ   1024          // H*W
#define DIMC  384
#define DIC   768           // 2*DIM
#define MLPD  1536          // 4*DIM
#define TOK   (NB*SEQ)      // 32768 tokens

// ---------------- scratch (device globals; no runtime alloc) ------------
__device__ float g_xn [(size_t)TOK*DIMC];
__device__ __align__(16) __half g_xs [(size_t)TOK*DIMC];
__device__ float g_hg [(size_t)TOK*3072];      // [tok][dir*1536 + {hid,gate}]
__device__ __align__(16) __half g_e  [(size_t)TOK*1536];      // [tok][dir*768 + c]
__device__ float g_y  [(size_t)TOK*DIMC];
__device__ __align__(16) __half g_yn [(size_t)TOK*DIMC];
__device__ __align__(16) __half g_yh [(size_t)TOK*MLPD];
// transposed weights (K-major, [N][K]) for the B operand, fp16
__device__ __align__(16) __half g_wT  [(size_t)3072*DIMC];
__device__ __align__(16) __half g_oT  [(size_t)DIMC*1536];    // cols 0-767 o1^T, 768-1535 o2^T
__device__ __align__(16) __half g_p1T [(size_t)MLPD*DIMC];
__device__ __align__(16) __half g_p2T [(size_t)DIMC*MLPD];

// ================= small helpers ========================================
__device__ __forceinline__ uint32_t smem_to_u32(const void* p) {
    uint32_t a;
    asm("{ .reg .u64 t; cvta.to.shared.u64 t, %1; cvt.u32.u64 %0, t; }"
        : "=r"(a) : "l"(p));
    return a;
}
__device__ __forceinline__ uint32_t lds32(uint32_t a) {
    uint32_t v;
    asm volatile("ld.shared.b32 %0, [%1];" : "=r"(v) : "r"(a));
    return v;
}
#define CP_ASYNC16(dst, src) \
    asm volatile("cp.async.cg.shared.global [%0], [%1], 16;" \
                 :: "r"(dst), "l"(src) : "memory")
#define CP_COMMIT() asm volatile("cp.async.commit_group;" ::: "memory")
#define CP_WAIT(n)  asm volatile("cp.async.wait_group %0;" :: "n"(n) : "memory")

#define MMA_F16(d, a0,a1,a2,a3, b0,b1)                                      \
    asm volatile(                                                           \
        "mma.sync.aligned.m16n8k16.row.col.f32.f16.f16.f32 "                \
        "{%0,%1,%2,%3}, {%4,%5,%6,%7}, {%8,%9}, {%0,%1,%2,%3};\n"           \
        : "+f"(d[0]), "+f"(d[1]), "+f"(d[2]), "+f"(d[3])                    \
        : "r"(a0), "r"(a1), "r"(a2), "r"(a3), "r"(b0), "r"(b1))

// ---------------- layer norm: one warp per token row ---------------------
template<typename OT>
__global__ __launch_bounds__(256) void ln_kernel(
    const float* __restrict__ x, const float* __restrict__ gamma,
    const float* __restrict__ beta, OT* __restrict__ out, int rows)
{
    int gw   = (blockIdx.x * blockDim.x + threadIdx.x) >> 5;
    int lane = threadIdx.x & 31;
    if (gw >= rows) return;
    const float* xr = x + (size_t)gw * DIMC;
    float s = 0.f, s2 = 0.f;
    #pragma unroll
    for (int i = lane; i < DIMC; i += 32) { float v = xr[i]; s += v; s2 += v*v; }
    #pragma unroll
    for (int o = 16; o; o >>= 1) {
        s  += __shfl_xor_sync(0xffffffffu, s,  o);
        s2 += __shfl_xor_sync(0xffffffffu, s2, o);
    }
    float mu  = s * (1.f/DIMC);
    float var = s2 * (1.f/DIMC) - mu*mu;
    float inv = rsqrtf(var + 1e-5f);
    OT* orow = out + (size_t)gw * DIMC;
    #pragma unroll
    for (int i = lane; i < DIMC; i += 32)
        orow[i] = (OT)((xr[i] - mu) * inv * gamma[i] + beta[i]);
}

// ---------------- depthwise 3x3 conv, NHWC, pad=1; 4 ch/thread ----------
__global__ __launch_bounds__(256) void dwconv_kernel(
    const float* __restrict__ xn, const float* __restrict__ w,
    const float* __restrict__ b, __half* __restrict__ xs)
{
    int idx = blockIdx.x * blockDim.x + threadIdx.x;   // 0 .. TOK*DIMC/4-1
    if (idx >= TOK*(DIMC/4)) return;
    int c4 = idx % (DIMC/4);
    int p  = idx / (DIMC/4);
    int c  = c4 * 4;
    int xq = p % WW;
    int yq = (p / WW) % HH;
    int n  = p / SEQ;

    float4 bb = *(const float4*)(b + c);
    float a0 = bb.x, a1 = bb.y, a2 = bb.z, a3 = bb.w;
    const float* w0 = w + (c+0)*9;
    const float* w1 = w + (c+1)*9;
    const float* w2 = w + (c+2)*9;
    const float* w3 = w + (c+3)*9;

    #pragma unroll
    for (int ky = 0; ky < 3; ky++) {
        int yy = yq + ky - 1;
        if (yy < 0 || yy >= HH) continue;
        #pragma unroll
        for (int kx = 0; kx < 3; kx++) {
            int xx = xq + kx - 1;
            if (xx < 0 || xx >= WW) continue;
            float4 v = *(const float4*)(xn + ((size_t)n*SEQ + yy*WW + xx)*DIMC + c);
            int t = ky*3 + kx;
            a0 = fmaf(w0[t], v.x, a0);
            a1 = fmaf(w1[t], v.y, a1);
            a2 = fmaf(w2[t], v.z, a2);
            a3 = fmaf(w3[t], v.w, a3);
        }
    }
    __half2 h01 = __floats2half2_rn(a0, a1);
    __half2 h23 = __floats2half2_rn(a2, a3);
    uint2 pk;
    pk.x = *(uint32_t*)&h01;
    pk.y = *(uint32_t*)&h23;
    *(uint2*)(xs + (size_t)p*DIMC + c) = pk;
}

// ---------------- all 6 weight transposes [K,N]->fp16 [N,K(stride)] ------
struct TransParams {
    const float* in[6];
    __half*      out[6];
    int K[6], N[6], ostr[6];
};
__global__ __launch_bounds__(256) void transpose_all_kernel(TransParams tp)
{
    int id = blockIdx.z;
    int K = tp.K[id], N = tp.N[id], ostr = tp.ostr[id];
    int kb = blockIdx.x * 32, nb = blockIdx.y * 32;
    if (kb >= K || nb >= N) return;
    const float* in = tp.in[id];
    __half* out = tp.out[id];
    __shared__ float t[32][33];
    int tx = threadIdx.x & 31, ty = threadIdx.x >> 5;   // 32 x 8
    #pragma unroll
    for (int i = 0; i < 32; i += 8)
        t[ty+i][tx] = in[(size_t)(kb+ty+i)*N + nb+tx];
    __syncthreads();
    #pragma unroll
    for (int i = 0; i < 32; i += 8)
        out[(size_t)(nb+ty+i)*ostr + kb+tx] = __float2half(t[tx][ty+i]);
}

// ---------------- fp16 tensor GEMM, K-tile 64, 3-stage, reg ping-pong ----
// C[M,N] = act(A[M,K] @ Bt[N,K]^T + bias) + add.  ACT: 0=none, 1=exact GELU.
// CTA: 128 threads, tile 128 x 128. 4 warps as 2(m) x 2(n); warp tile 64x64.
#define STAGES 3
#define APITCH 144                 // 64 halves (128B) + 16B pad
#define ABYTES (128*APITCH)
#define STB    (2*ABYTES)
#define GSMEM  (STAGES*STB)        // 110592

template<int ACT, typename CT>
__global__ __launch_bounds__(128) void tc_gemm(
    const __half* __restrict__ A, const __half* __restrict__ Bt,
    const float* __restrict__ bias, const float* __restrict__ addp,
    CT* __restrict__ C, int M, int N, int K)
{
    extern __shared__ char smem[];
    const uint32_t sbase = smem_to_u32(smem);

    const int tid  = threadIdx.x;
    const int wid  = tid >> 5;
    const int lane = tid & 31;
    const int wm   = wid & 1;                // warp m (2)
    const int wn   = wid >> 1;               // warp n (2)
    const int gid  = lane >> 2;              // 0..7
    const int tig  = lane & 3;               // 0..3
    const int m0   = blockIdx.y * 128;
    const int n0   = blockIdx.x * 128;
    const int nk   = K >> 6;                 // 64-k tiles

    float acc[4][8][4];
    #pragma unroll
    for (int mi = 0; mi < 4; mi++)
        #pragma unroll
        for (int ni = 0; ni < 8; ni++)
            #pragma unroll
            for (int q = 0; q < 4; q++) acc[mi][ni][q] = 0.f;

    // ---- tile loader: global -> smem stage via cp.async (16B = 8 halves) --
    auto load_tile = [&](int i) {
        uint32_t sa = sbase + (i % STAGES) * STB;
        uint32_t sb = sa + ABYTES;
        const __half* Ag = A  + (size_t)m0 * K + i*64;
        const __half* Bg = Bt + (size_t)n0 * K + i*64;
        #pragma unroll
        for (int t = 0; t < 8; t++) {                 // A: 1024 chunks
            int f = tid + t*128;
            int r = f >> 3, kc = f & 7;
            CP_ASYNC16(sa + r*APITCH + kc*16, Ag + (size_t)r*K + kc*8);
        }
        #pragma unroll
        for (int t = 0; t < 8; t++) {                 // B: 1024 chunks
            int f = tid + t*128;
            int r = f >> 3, kc = f & 7;
            CP_ASYNC16(sb + r*APITCH + kc*16, Bg + (size_t)r*K + kc*8);
        }
    };

    load_tile(0); CP_COMMIT();
    load_tile(1); CP_COMMIT();

    uint32_t af[2][4][4];
    uint32_t bf[2][8][2];

    for (int i = 0; i < nk; i++) {
        CP_WAIT(1);
        __syncthreads();
        if (i + 2 < nk) load_tile(i + 2);
        CP_COMMIT();

        uint32_t sa = sbase + (i % STAGES) * STB;
        uint32_t sb = sa + ABYTES;
        const uint32_t abase = sa + (wm*64 + gid)*APITCH + tig*4;
        const uint32_t bbase = sb + (wn*64 + gid)*APITCH + tig*4;

        // prefetch ks=0 fragments into buffer 0
        #pragma unroll
        for (int mi = 0; mi < 4; mi++) {
            uint32_t ba = abase + mi*16*APITCH;
            af[0][mi][0] = lds32(ba);
            af[0][mi][1] = lds32(ba + 8*APITCH);
            af[0][mi][2] = lds32(ba + 16);
            af[0][mi][3] = lds32(ba + 8*APITCH + 16);
        }
        #pragma unroll
        for (int ni = 0; ni < 8; ni++) {
            uint32_t bb = bbase + ni*8*APITCH;
            bf[0][ni][0] = lds32(bb);
            bf[0][ni][1] = lds32(bb + 16);
        }

        #pragma unroll
        for (int ks = 0; ks < 4; ks++) {
            int cur = ks & 1, nxt = cur ^ 1;
            if (ks < 3) {
                uint32_t ko = (ks+1)*32;   // 16 halves = 32 bytes per k16 step
                #pragma unroll
                for (int mi = 0; mi < 4; mi++) {
                    uint32_t ba = abase + mi*16*APITCH + ko;
                    af[nxt][mi][0] = lds32(ba);
                    af[nxt][mi][1] = lds32(ba + 8*APITCH);
                    af[nxt][mi][2] = lds32(ba + 16);
                    af[nxt][mi][3] = lds32(ba + 8*APITCH + 16);
                }
                #pragma unroll
                for (int ni = 0; ni < 8; ni++) {
                    uint32_t bb = bbase + ni*8*APITCH + ko;
                    bf[nxt][ni][0] = lds32(bb);
                    bf[nxt][ni][1] = lds32(bb + 16);
                }
            }
            #pragma unroll
            for (int mi = 0; mi < 4; mi++)
                #pragma unroll
                for (int ni = 0; ni < 8; ni++)
                    MMA_F16(acc[mi][ni],
                            af[cur][mi][0], af[cur][mi][1], af[cur][mi][2], af[cur][mi][3],
                            bf[cur][ni][0], bf[cur][ni][1]);
        }
    }

    // ---- epilogue ---------------------------------------------------------
    #pragma unroll
    for (int mi = 0; mi < 4; mi++) {
        int r0 = m0 + wm*64 + mi*16 + gid;
        #pragma unroll
        for (int ni = 0; ni < 8; ni++) {
            int cn = n0 + wn*64 + ni*8 + tig*2;
            #pragma unroll
            for (int half = 0; half < 2; half++) {
                int r = r0 + half*8;
                float v0 = acc[mi][ni][half*2+0];
                float v1 = acc[mi][ni][half*2+1];
                if (bias) { v0 += bias[cn]; v1 += bias[cn+1]; }
                if (ACT == 1) {
                    v0 = 0.5f * v0 * (1.f + erff(v0 * 0.70710678118654752f));
                    v1 = 0.5f * v1 * (1.f + erff(v1 * 0.70710678118654752f));
                }
                if (addp) {
                    float2 ad = *(const float2*)(addp + (size_t)r*N + cn);
                    v0 += ad.x; v1 += ad.y;
                }
                if (sizeof(CT) == 2) {
                    __half2 hv = __floats2half2_rn(v0, v1);
                    *(__half2*)((__half*)C + (size_t)r*N + cn) = hv;
                } else {
                    float2 ov; ov.x = v0; ov.y = v1;
                    *(float2*)((float*)C + (size_t)r*N + cn) = ov;
                }
            }
        }
    }
}

// ---------------- minGRU scans, LINEAR domain ----------------------------
// log-space reference == h_t = sigmoid(-gate)*h_{t-1} + sigmoid(gate)*g(hid)
// with g(x) = x>=0 ? x+0.5 : sigmoid(x)   [exp(-softplus(-x)) = sigmoid(x)]
// Serial chain is a single FMA; all sigmoid work pipelines across steps.
__global__ __launch_bounds__(256) void scan_kernel(
    const float* __restrict__ hg, __half* __restrict__ e)
{
    int idx = blockIdx.x * blockDim.x + threadIdx.x;   // 0 .. 2*NB*DIC-1
    int dir = idx / (NB*DIC);
    int r   = idx % (NB*DIC);
    int n   = r / DIC;
    int c   = r % DIC;
    const int coff  = dir * 1536 + c;                  // hid col; gate at +768
    const int eoff  = dir * 768 + c;
    const size_t base  = (size_t)n * SEQ * 3072;
    const size_t ebase = (size_t)n * SEQ * 1536;

    float h = 0.f;
    int t0  = dir ? SEQ-1 : 0;
    int dt  = dir ? -1 : 1;
    for (int s = 0; s < SEQ; s++) {
        int t = t0 + s*dt;
        size_t row = base + (size_t)t * 3072;
        float hid  = hg[row + coff];
        float gate = hg[row + coff + 768];
        float cs = __fdividef(1.f, 1.f + __expf(gate));        // sigmoid(-gate)
        float g  = (hid >= 0.f) ? (hid + 0.5f)
                                : __fdividef(1.f, 1.f + __expf(-hid));
        float v  = (1.f - cs) * g;
        h = fmaf(cs, h, v);
        e[ebase + (size_t)t*1536 + eoff] = __float2half(h);
    }
}

// ---------------- launch -------------------------------------------------
extern "C" void kernel_launch(void* const* d_in, const int* in_sizes, int n_in,
                              void* d_out, int out_size)
{
    const float* x        = (const float*)d_in[0];
    const float* gamma1   = (const float*)d_in[1];
    const float* beta1    = (const float*)d_in[2];
    const float* dwc_w    = (const float*)d_in[3];
    const float* dwc_b    = (const float*)d_in[4];
    const float* gru1_w   = (const float*)d_in[5];
    const float* gru1_out = (const float*)d_in[6];
    const float* gru2_w   = (const float*)d_in[7];
    const float* gru2_out = (const float*)d_in[8];
    const float* gamma2   = (const float*)d_in[9];
    const float* beta2    = (const float*)d_in[10];
    const float* p1_w     = (const float*)d_in[11];
    const float* p1_b     = (const float*)d_in[12];
    const float* p2_w     = (const float*)d_in[13];
    const float* p2_b     = (const float*)d_in[14];
    float* out = (float*)d_out;

    float *xn, *hg, *y;
    __half *xs, *e, *yn, *yh, *wT, *oT, *p1T, *p2T;
    cudaGetSymbolAddress((void**)&xn,  g_xn);
    cudaGetSymbolAddress((void**)&xs,  g_xs);
    cudaGetSymbolAddress((void**)&hg,  g_hg);
    cudaGetSymbolAddress((void**)&e,   g_e);
    cudaGetSymbolAddress((void**)&y,   g_y);
    cudaGetSymbolAddress((void**)&yn,  g_yn);
    cudaGetSymbolAddress((void**)&yh,  g_yh);
    cudaGetSymbolAddress((void**)&wT,  g_wT);
    cudaGetSymbolAddress((void**)&oT,  g_oT);
    cudaGetSymbolAddress((void**)&p1T, g_p1T);
    cudaGetSymbolAddress((void**)&p2T, g_p2T);

    cudaFuncSetAttribute(tc_gemm<0,float>,  cudaFuncAttributeMaxDynamicSharedMemorySize, GSMEM);
    cudaFuncSetAttribute(tc_gemm<1,__half>, cudaFuncAttributeMaxDynamicSharedMemorySize, GSMEM);

    // 0. all weight transposes in one launch (K-major fp16 B operands)
    {
        TransParams tp;
        tp.in[0]=gru1_w;   tp.out[0]=wT;                      tp.K[0]=DIMC; tp.N[0]=2*DIC; tp.ostr[0]=DIMC;
        tp.in[1]=gru2_w;   tp.out[1]=wT+(size_t)1536*DIMC;    tp.K[1]=DIMC; tp.N[1]=2*DIC; tp.ostr[1]=DIMC;
        tp.in[2]=gru1_out; tp.out[2]=oT;                      tp.K[2]=DIC;  tp.N[2]=DIMC;  tp.ostr[2]=1536;
        tp.in[3]=gru2_out; tp.out[3]=oT+768;                  tp.K[3]=DIC;  tp.N[3]=DIMC;  tp.ostr[3]=1536;
        tp.in[4]=p1_w;     tp.out[4]=p1T;                     tp.K[4]=DIMC; tp.N[4]=MLPD;  tp.ostr[4]=DIMC;
        tp.in[5]=p2_w;     tp.out[5]=p2T;                     tp.K[5]=MLPD; tp.N[5]=DIMC;  tp.ostr[5]=MLPD;
        transpose_all_kernel<<<dim3(48, 48, 6), 256>>>(tp);
    }
    // 1. LN1 (f32 out -> conv input)
    ln_kernel<float><<<(TOK*32 + 255)/256, 256>>>(x, gamma1, beta1, xn, TOK);
    // 2. depthwise conv 3x3 (fp16 out, 4 ch/thread)
    dwconv_kernel<<<(TOK*(DIMC/4) + 255)/256, 256>>>(xn, dwc_w, dwc_b, xs);
    // 3. fused GRU input projections: hg = xs @ [W1|W2]  (N=3072, K=384), f32 out
    tc_gemm<0,float><<<dim3(3072/128, TOK/128), 128, GSMEM>>>(
        xs, wT, nullptr, nullptr, hg, TOK, 3072, DIMC);
    // 4. forward + backward minGRU scans (linear domain) -> e[tok][1536] fp16
    scan_kernel<<<(2*NB*DIC)/256, 256>>>(hg, e);
    // 5. fused output projections + residual: y = e @ [O1;O2] + x  (K=1536), f32
    tc_gemm<0,float><<<dim3(DIMC/128, TOK/128), 128, GSMEM>>>(
        e, oT, nullptr, x, y, TOK, DIMC, 1536);
    // 6. LN2 (fp16 out)
    ln_kernel<__half><<<(TOK*32 + 255)/256, 256>>>(y, gamma2, beta2, yn, TOK);
    // 7. MLP up + exact GELU (fp16 out)
    tc_gemm<1,__half><<<dim3(MLPD/128, TOK/128), 128, GSMEM>>>(
        yn, p1T, p1_b, nullptr, yh, TOK, MLPD, DIMC);
    // 8. MLP down + bias + residual -> out (f32)
    tc_gemm<0,float><<<dim3(DIMC/128, TOK/128), 128, GSMEM>>>(
        yh, p2T, p2_b, y, out, TOK, DIMC, MLPD);
}

// round 11
// speedup vs baseline: 5.5533x; 1.0076x over previous
#include <cuda_runtime.h>
#include <cuda_fp16.h>
#include <math.h>
#include <stdint.h>

// ---------------- problem constants (fixed by reference) ----------------
#define NB    32
#define HH    32
#define WW    32
#define SEQ   1024          // H*W
#define DIMC  384
#define DIC   768           // 2*DIM
#define MLPD  1536          // 4*DIM
#define TOK   (NB*SEQ)      // 32768 tokens

// ---------------- scratch (device globals; no runtime alloc) ------------
__device__ __align__(16) __half g_xn [(size_t)TOK*DIMC];
__device__ __align__(16) __half g_xs [(size_t)TOK*DIMC];
__device__ __align__(16) __half g_hg [(size_t)TOK*3072];   // [tok][dir*1536+{hid,gate}]
__device__ __align__(16) __half g_e  [(size_t)TOK*1536];   // [tok][dir*768 + c]
__device__ float g_y  [(size_t)TOK*DIMC];
__device__ __align__(16) __half g_yn [(size_t)TOK*DIMC];
__device__ __align__(16) __half g_yh [(size_t)TOK*MLPD];
// transposed weights (K-major, [N][K]) for the B operand, fp16
__device__ __align__(16) __half g_wT  [(size_t)3072*DIMC];
__device__ __align__(16) __half g_oT  [(size_t)DIMC*1536]; // cols 0-767 o1^T, 768-1535 o2^T
__device__ __align__(16) __half g_p1T [(size_t)MLPD*DIMC];
__device__ __align__(16) __half g_p2T [(size_t)DIMC*MLPD];

// ================= small helpers ========================================
__device__ __forceinline__ uint32_t smem_to_u32(const void* p) {
    uint32_t a;
    asm("{ .reg .u64 t; cvta.to.shared.u64 t, %1; cvt.u32.u64 %0, t; }"
        : "=r"(a) : "l"(p));
    return a;
}
__device__ __forceinline__ uint32_t lds32(uint32_t a) {
    uint32_t v;
    asm volatile("ld.shared.b32 %0, [%1];" : "=r"(v) : "r"(a));
    return v;
}
#define CP_ASYNC16(dst, src) \
    asm volatile("cp.async.cg.shared.global [%0], [%1], 16;" \
                 :: "r"(dst), "l"(src) : "memory")
#define CP_COMMIT() asm volatile("cp.async.commit_group;" ::: "memory")
#define CP_WAIT(n)  asm volatile("cp.async.wait_group %0;" :: "n"(n) : "memory")

#define MMA_F16(d, a0,a1,a2,a3, b0,b1)                                      \
    asm volatile(                                                           \
        "mma.sync.aligned.m16n8k16.row.col.f32.f16.f16.f32 "                \
        "{%0,%1,%2,%3}, {%4,%5,%6,%7}, {%8,%9}, {%0,%1,%2,%3};\n"           \
        : "+f"(d[0]), "+f"(d[1]), "+f"(d[2]), "+f"(d[3])                    \
        : "r"(a0), "r"(a1), "r"(a2), "r"(a3), "r"(b0), "r"(b1))

// ---------------- layer norm: one warp per token row ---------------------
template<typename OT>
__global__ __launch_bounds__(256) void ln_kernel(
    const float* __restrict__ x, const float* __restrict__ gamma,
    const float* __restrict__ beta, OT* __restrict__ out, int rows)
{
    int gw   = (blockIdx.x * blockDim.x + threadIdx.x) >> 5;
    int lane = threadIdx.x & 31;
    if (gw >= rows) return;
    const float* xr = x + (size_t)gw * DIMC;
    float s = 0.f, s2 = 0.f;
    #pragma unroll
    for (int i = lane; i < DIMC; i += 32) { float v = xr[i]; s += v; s2 += v*v; }
    #pragma unroll
    for (int o = 16; o; o >>= 1) {
        s  += __shfl_xor_sync(0xffffffffu, s,  o);
        s2 += __shfl_xor_sync(0xffffffffu, s2, o);
    }
    float mu  = s * (1.f/DIMC);
    float var = s2 * (1.f/DIMC) - mu*mu;
    float inv = rsqrtf(var + 1e-5f);
    OT* orow = out + (size_t)gw * DIMC;
    #pragma unroll
    for (int i = lane; i < DIMC; i += 32)
        orow[i] = (OT)((xr[i] - mu) * inv * gamma[i] + beta[i]);
}

// ---------------- depthwise 3x3 conv, NHWC, pad=1; 4 ch/thread, fp16 in --
__global__ __launch_bounds__(256) void dwconv_kernel(
    const __half* __restrict__ xn, const float* __restrict__ w,
    const float* __restrict__ b, __half* __restrict__ xs)
{
    int idx = blockIdx.x * blockDim.x + threadIdx.x;   // 0 .. TOK*DIMC/4-1
    if (idx >= TOK*(DIMC/4)) return;
    int c4 = idx % (DIMC/4);
    int p  = idx / (DIMC/4);
    int c  = c4 * 4;
    int xq = p % WW;
    int yq = (p / WW) % HH;
    int n  = p / SEQ;

    float4 bb = *(const float4*)(b + c);
    float a0 = bb.x, a1 = bb.y, a2 = bb.z, a3 = bb.w;
    const float* w0 = w + (c+0)*9;
    const float* w1 = w + (c+1)*9;
    const float* w2 = w + (c+2)*9;
    const float* w3 = w + (c+3)*9;

    #pragma unroll
    for (int ky = 0; ky < 3; ky++) {
        int yy = yq + ky - 1;
        if (yy < 0 || yy >= HH) continue;
        #pragma unroll
        for (int kx = 0; kx < 3; kx++) {
            int xx = xq + kx - 1;
            if (xx < 0 || xx >= WW) continue;
            uint2 pk = *(const uint2*)(xn + ((size_t)n*SEQ + yy*WW + xx)*DIMC + c);
            float2 f01 = __half22float2(*(__half2*)&pk.x);
            float2 f23 = __half22float2(*(__half2*)&pk.y);
            int t = ky*3 + kx;
            a0 = fmaf(w0[t], f01.x, a0);
            a1 = fmaf(w1[t], f01.y, a1);
            a2 = fmaf(w2[t], f23.x, a2);
            a3 = fmaf(w3[t], f23.y, a3);
        }
    }
    __half2 h01 = __floats2half2_rn(a0, a1);
    __half2 h23 = __floats2half2_rn(a2, a3);
    uint2 pk;
    pk.x = *(uint32_t*)&h01;
    pk.y = *(uint32_t*)&h23;
    *(uint2*)(xs + (size_t)p*DIMC + c) = pk;
}

// ---------------- all 6 weight transposes [K,N]->fp16 [N,K(stride)] ------
struct TransParams {
    const float* in[6];
    __half*      out[6];
    int K[6], N[6], ostr[6];
};
__global__ __launch_bounds__(256) void transpose_all_kernel(TransParams tp)
{
    int id = blockIdx.z;
    int K = tp.K[id], N = tp.N[id], ostr = tp.ostr[id];
    int kb = blockIdx.x * 32, nb = blockIdx.y * 32;
    if (kb >= K || nb >= N) return;
    const float* in = tp.in[id];
    __half* out = tp.out[id];
    __shared__ float t[32][33];
    int tx = threadIdx.x & 31, ty = threadIdx.x >> 5;   // 32 x 8
    #pragma unroll
    for (int i = 0; i < 32; i += 8)
        t[ty+i][tx] = in[(size_t)(kb+ty+i)*N + nb+tx];
    __syncthreads();
    #pragma unroll
    for (int i = 0; i < 32; i += 8)
        out[(size_t)(nb+ty+i)*ostr + kb+tx] = __float2half(t[tx][ty+i]);
}

// ---------------- fp16 tensor GEMM, K-tile 64, 3-stage, reg ping-pong ----
// C[M,N] = act(A[M,K] @ Bt[N,K]^T + bias) + add.  ACT: 0=none, 1=exact GELU.
// CTA: 128 threads, tile 128 x 128. 4 warps as 2(m) x 2(n); warp tile 64x64.
#define STAGES 3
#define APITCH 144                 // 64 halves (128B) + 16B pad
#define ABYTES (128*APITCH)
#define STB    (2*ABYTES)
#define GSMEM  (STAGES*STB)        // 110592

template<int ACT, typename CT>
__global__ __launch_bounds__(128) void tc_gemm(
    const __half* __restrict__ A, const __half* __restrict__ Bt,
    const float* __restrict__ bias, const float* __restrict__ addp,
    CT* __restrict__ C, int M, int N, int K)
{
    extern __shared__ char smem[];
    const uint32_t sbase = smem_to_u32(smem);

    const int tid  = threadIdx.x;
    const int wid  = tid >> 5;
    const int lane = tid & 31;
    const int wm   = wid & 1;                // warp m (2)
    const int wn   = wid >> 1;               // warp n (2)
    const int gid  = lane >> 2;              // 0..7
    const int tig  = lane & 3;               // 0..3
    const int m0   = blockIdx.y * 128;
    const int n0   = blockIdx.x * 128;
    const int nk   = K >> 6;                 // 64-k tiles

    float acc[4][8][4];
    #pragma unroll
    for (int mi = 0; mi < 4; mi++)
        #pragma unroll
        for (int ni = 0; ni < 8; ni++)
            #pragma unroll
            for (int q = 0; q < 4; q++) acc[mi][ni][q] = 0.f;

    // ---- tile loader: global -> smem stage via cp.async (16B = 8 halves) --
    auto load_tile = [&](int i) {
        uint32_t sa = sbase + (i % STAGES) * STB;
        uint32_t sb = sa + ABYTES;
        const __half* Ag = A  + (size_t)m0 * K + i*64;
        const __half* Bg = Bt + (size_t)n0 * K + i*64;
        #pragma unroll
        for (int t = 0; t < 8; t++) {                 // A: 1024 chunks
            int f = tid + t*128;
            int r = f >> 3, kc = f & 7;
            CP_ASYNC16(sa + r*APITCH + kc*16, Ag + (size_t)r*K + kc*8);
        }
        #pragma unroll
        for (int t = 0; t < 8; t++) {                 // B: 1024 chunks
            int f = tid + t*128;
            int r = f >> 3, kc = f & 7;
            CP_ASYNC16(sb + r*APITCH + kc*16, Bg + (size_t)r*K + kc*8);
        }
    };

    load_tile(0); CP_COMMIT();
    load_tile(1); CP_COMMIT();

    uint32_t af[2][4][4];
    uint32_t bf[2][8][2];

    for (int i = 0; i < nk; i++) {
        CP_WAIT(1);
        __syncthreads();
        if (i + 2 < nk) load_tile(i + 2);
        CP_COMMIT();

        uint32_t sa = sbase + (i % STAGES) * STB;
        uint32_t sb = sa + ABYTES;
        const uint32_t abase = sa + (wm*64 + gid)*APITCH + tig*4;
        const uint32_t bbase = sb + (wn*64 + gid)*APITCH + tig*4;

        // prefetch ks=0 fragments into buffer 0
        #pragma unroll
        for (int mi = 0; mi < 4; mi++) {
            uint32_t ba = abase + mi*16*APITCH;
            af[0][mi][0] = lds32(ba);
            af[0][mi][1] = lds32(ba + 8*APITCH);
            af[0][mi][2] = lds32(ba + 16);
            af[0][mi][3] = lds32(ba + 8*APITCH + 16);
        }
        #pragma unroll
        for (int ni = 0; ni < 8; ni++) {
            uint32_t bb = bbase + ni*8*APITCH;
            bf[0][ni][0] = lds32(bb);
            bf[0][ni][1] = lds32(bb + 16);
        }

        #pragma unroll
        for (int ks = 0; ks < 4; ks++) {
            int cur = ks & 1, nxt = cur ^ 1;
            if (ks < 3) {
                uint32_t ko = (ks+1)*32;   // 16 halves = 32 bytes per k16 step
                #pragma unroll
                for (int mi = 0; mi < 4; mi++) {
                    uint32_t ba = abase + mi*16*APITCH + ko;
                    af[nxt][mi][0] = lds32(ba);
                    af[nxt][mi][1] = lds32(ba + 8*APITCH);
                    af[nxt][mi][2] = lds32(ba + 16);
                    af[nxt][mi][3] = lds32(ba + 8*APITCH + 16);
                }
                #pragma unroll
                for (int ni = 0; ni < 8; ni++) {
                    uint32_t bb = bbase + ni*8*APITCH + ko;
                    bf[nxt][ni][0] = lds32(bb);
                    bf[nxt][ni][1] = lds32(bb + 16);
                }
            }
            #pragma unroll
            for (int mi = 0; mi < 4; mi++)
                #pragma unroll
                for (int ni = 0; ni < 8; ni++)
                    MMA_F16(acc[mi][ni],
                            af[cur][mi][0], af[cur][mi][1], af[cur][mi][2], af[cur][mi][3],
                            bf[cur][ni][0], bf[cur][ni][1]);
        }
    }

    // ---- epilogue ---------------------------------------------------------
    #pragma unroll
    for (int mi = 0; mi < 4; mi++) {
        int r0 = m0 + wm*64 + mi*16 + gid;
        #pragma unroll
        for (int ni = 0; ni < 8; ni++) {
            int cn = n0 + wn*64 + ni*8 + tig*2;
            #pragma unroll
            for (int half = 0; half < 2; half++) {
                int r = r0 + half*8;
                float v0 = acc[mi][ni][half*2+0];
                float v1 = acc[mi][ni][half*2+1];
                if (bias) { v0 += bias[cn]; v1 += bias[cn+1]; }
                if (ACT == 1) {
                    v0 = 0.5f * v0 * (1.f + erff(v0 * 0.70710678118654752f));
                    v1 = 0.5f * v1 * (1.f + erff(v1 * 0.70710678118654752f));
                }
                if (addp) {
                    float2 ad = *(const float2*)(addp + (size_t)r*N + cn);
                    v0 += ad.x; v1 += ad.y;
                }
                if (sizeof(CT) == 2) {
                    __half2 hv = __floats2half2_rn(v0, v1);
                    *(__half2*)((__half*)C + (size_t)r*N + cn) = hv;
                } else {
                    float2 ov; ov.x = v0; ov.y = v1;
                    *(float2*)((float*)C + (size_t)r*N + cn) = ov;
                }
            }
        }
    }
}

// ---------------- minGRU scans, LINEAR domain, fp16 hg -------------------
// h_t = sigmoid(-gate)*h_{t-1} + sigmoid(gate)*g(hid)
// with g(x) = x>=0 ? x+0.5 : sigmoid(x)
__global__ __launch_bounds__(256) void scan_kernel(
    const __half* __restrict__ hg, __half* __restrict__ e)
{
    int idx = blockIdx.x * blockDim.x + threadIdx.x;   // 0 .. 2*NB*DIC-1
    int dir = idx / (NB*DIC);
    int r   = idx % (NB*DIC);
    int n   = r / DIC;
    int c   = r % DIC;
    const int coff  = dir * 1536 + c;                  // hid col; gate at +768
    const int eoff  = dir * 768 + c;
    const size_t base  = (size_t)n * SEQ * 3072;
    const size_t ebase = (size_t)n * SEQ * 1536;

    float h = 0.f;
    int t0  = dir ? SEQ-1 : 0;
    int dt  = dir ? -1 : 1;
    for (int s = 0; s < SEQ; s++) {
        int t = t0 + s*dt;
        size_t row = base + (size_t)t * 3072;
        float hid  = __half2float(hg[row + coff]);
        float gate = __half2float(hg[row + coff + 768]);
        float cs = __fdividef(1.f, 1.f + __expf(gate));        // sigmoid(-gate)
        float g  = (hid >= 0.f) ? (hid + 0.5f)
                                : __fdividef(1.f, 1.f + __expf(-hid));
        float v  = (1.f - cs) * g;
        h = fmaf(cs, h, v);
        e[ebase + (size_t)t*1536 + eoff] = __float2half(h);
    }
}

// ---------------- launch -------------------------------------------------
extern "C" void kernel_launch(void* const* d_in, const int* in_sizes, int n_in,
                              void* d_out, int out_size)
{
    const float* x        = (const float*)d_in[0];
    const float* gamma1   = (const float*)d_in[1];
    const float* beta1    = (const float*)d_in[2];
    const float* dwc_w    = (const float*)d_in[3];
    const float* dwc_b    = (const float*)d_in[4];
    const float* gru1_w   = (const float*)d_in[5];
    const float* gru1_out = (const float*)d_in[6];
    const float* gru2_w   = (const float*)d_in[7];
    const float* gru2_out = (const float*)d_in[8];
    const float* gamma2   = (const float*)d_in[9];
    const float* beta2    = (const float*)d_in[10];
    const float* p1_w     = (const float*)d_in[11];
    const float* p1_b     = (const float*)d_in[12];
    const float* p2_w     = (const float*)d_in[13];
    const float* p2_b     = (const float*)d_in[14];
    float* out = (float*)d_out;

    float *y;
    __half *xn, *xs, *hg, *e, *yn, *yh, *wT, *oT, *p1T, *p2T;
    cudaGetSymbolAddress((void**)&xn,  g_xn);
    cudaGetSymbolAddress((void**)&xs,  g_xs);
    cudaGetSymbolAddress((void**)&hg,  g_hg);
    cudaGetSymbolAddress((void**)&e,   g_e);
    cudaGetSymbolAddress((void**)&y,   g_y);
    cudaGetSymbolAddress((void**)&yn,  g_yn);
    cudaGetSymbolAddress((void**)&yh,  g_yh);
    cudaGetSymbolAddress((void**)&wT,  g_wT);
    cudaGetSymbolAddress((void**)&oT,  g_oT);
    cudaGetSymbolAddress((void**)&p1T, g_p1T);
    cudaGetSymbolAddress((void**)&p2T, g_p2T);

    cudaFuncSetAttribute(tc_gemm<0,float>,  cudaFuncAttributeMaxDynamicSharedMemorySize, GSMEM);
    cudaFuncSetAttribute(tc_gemm<0,__half>, cudaFuncAttributeMaxDynamicSharedMemorySize, GSMEM);
    cudaFuncSetAttribute(tc_gemm<1,__half>, cudaFuncAttributeMaxDynamicSharedMemorySize, GSMEM);

    // 0. all weight transposes in one launch (K-major fp16 B operands)
    {
        TransParams tp;
        tp.in[0]=gru1_w;   tp.out[0]=wT;                      tp.K[0]=DIMC; tp.N[0]=2*DIC; tp.ostr[0]=DIMC;
        tp.in[1]=gru2_w;   tp.out[1]=wT+(size_t)1536*DIMC;    tp.K[1]=DIMC; tp.N[1]=2*DIC; tp.ostr[1]=DIMC;
        tp.in[2]=gru1_out; tp.out[2]=oT;                      tp.K[2]=DIC;  tp.N[2]=DIMC;  tp.ostr[2]=1536;
        tp.in[3]=gru2_out; tp.out[3]=oT+768;                  tp.K[3]=DIC;  tp.N[3]=DIMC;  tp.ostr[3]=1536;
        tp.in[4]=p1_w;     tp.out[4]=p1T;                     tp.K[4]=DIMC; tp.N[4]=MLPD;  tp.ostr[4]=DIMC;
        tp.in[5]=p2_w;     tp.out[5]=p2T;                     tp.K[5]=MLPD; tp.N[5]=DIMC;  tp.ostr[5]=MLPD;
        transpose_all_kernel<<<dim3(48, 48, 6), 256>>>(tp);
    }
    // 1. LN1 (fp16 out -> conv input)
    ln_kernel<__half><<<(TOK*32 + 255)/256, 256>>>(x, gamma1, beta1, xn, TOK);
    // 2. depthwise conv 3x3 (fp16 in/out, 4 ch/thread)
    dwconv_kernel<<<(TOK*(DIMC/4) + 255)/256, 256>>>(xn, dwc_w, dwc_b, xs);
    // 3. fused GRU input projections: hg = xs @ [W1|W2]  (N=3072, K=384), fp16 out
    tc_gemm<0,__half><<<dim3(3072/128, TOK/128), 128, GSMEM>>>(
        xs, wT, nullptr, nullptr, hg, TOK, 3072, DIMC);
    // 4. forward + backward minGRU scans (linear domain) -> e[tok][1536] fp16
    scan_kernel<<<(2*NB*DIC)/256, 256>>>(hg, e);
    // 5. fused output projections + residual: y = e @ [O1;O2] + x  (K=1536), f32
    tc_gemm<0,float><<<dim3(DIMC/128, TOK/128), 128, GSMEM>>>(
        e, oT, nullptr, x, y, TOK, DIMC, 1536);
    // 6. LN2 (fp16 out)
    ln_kernel<__half><<<(TOK*32 + 255)/256, 256>>>(y, gamma2, beta2, yn, TOK);
    // 7. MLP up + exact GELU (fp16 out)
    tc_gemm<1,__half><<<dim3(MLPD/128, TOK/128), 128, GSMEM>>>(
        yn, p1T, p1_b, nullptr, yh, TOK, MLPD, DIMC);
    // 8. MLP down + bias + residual -> out (f32)
    tc_gemm<0,float><<<dim3(DIMC/128, TOK/128), 128, GSMEM>>>(
        yh, p2T, p2_b, y, out, TOK, DIMC, MLPD);
}

// round 12
// speedup vs baseline: 5.7799x; 1.0408x over previous
#include <cuda_runtime.h>
#include <cuda_fp16.h>
#include <math.h>
#include <stdint.h>

// ---------------- problem constants (fixed by reference) ----------------
#define NB    32
#define HH    32
#define WW    32
#define SEQ   1024          // H*W
#define DIMC  384
#define DIC   768           // 2*DIM
#define MLPD  1536          // 4*DIM
#define TOK   (NB*SEQ)      // 32768 tokens

// ---------------- scratch (device globals; no runtime alloc) ------------
__device__ __align__(16) __half g_xn [(size_t)TOK*DIMC];
__device__ __align__(16) __half g_xs [(size_t)TOK*DIMC];
__device__ __align__(16) __half g_hg [(size_t)TOK*3072];   // [tok][dir*1536+{hid,gate}]
__device__ __align__(16) __half g_e  [(size_t)TOK*1536];   // [tok][dir*768 + c]
__device__ float g_y  [(size_t)TOK*DIMC];
__device__ __align__(16) __half g_yn [(size_t)TOK*DIMC];
__device__ __align__(16) __half g_yh [(size_t)TOK*MLPD];
// transposed weights (K-major, [N][K]) for the B operand, fp16
__device__ __align__(16) __half g_wT  [(size_t)3072*DIMC];
__device__ __align__(16) __half g_oT  [(size_t)DIMC*1536]; // cols 0-767 o1^T, 768-1535 o2^T
__device__ __align__(16) __half g_p1T [(size_t)MLPD*DIMC];
__device__ __align__(16) __half g_p2T [(size_t)DIMC*MLPD];

// ================= small helpers ========================================
__device__ __forceinline__ uint32_t smem_to_u32(const void* p) {
    uint32_t a;
    asm("{ .reg .u64 t; cvta.to.shared.u64 t, %1; cvt.u32.u64 %0, t; }"
        : "=r"(a) : "l"(p));
    return a;
}
#define CP_ASYNC16(dst, src) \
    asm volatile("cp.async.cg.shared.global [%0], [%1], 16;" \
                 :: "r"(dst), "l"(src) : "memory")
#define CP_COMMIT() asm volatile("cp.async.commit_group;" ::: "memory")
#define CP_WAIT(n)  asm volatile("cp.async.wait_group %0;" :: "n"(n) : "memory")

// ldmatrix x4: four 8x8 b16 tiles; lanes 0-7/8-15/16-23/24-31 address tiles 0-3
#define LDSM_X4(r0,r1,r2,r3, addr)                                          \
    asm volatile("ldmatrix.sync.aligned.m8n8.x4.shared.b16 {%0,%1,%2,%3}, [%4];" \
        : "=r"(r0), "=r"(r1), "=r"(r2), "=r"(r3) : "r"(addr))

#define MMA_F16(d, a0,a1,a2,a3, b0,b1)                                      \
    asm volatile(                                                           \
        "mma.sync.aligned.m16n8k16.row.col.f32.f16.f16.f32 "                \
        "{%0,%1,%2,%3}, {%4,%5,%6,%7}, {%8,%9}, {%0,%1,%2,%3};\n"           \
        : "+f"(d[0]), "+f"(d[1]), "+f"(d[2]), "+f"(d[3])                    \
        : "r"(a0), "r"(a1), "r"(a2), "r"(a3), "r"(b0), "r"(b1))

// ---------------- layer norm: one warp per token row ---------------------
template<typename OT>
__global__ __launch_bounds__(256) void ln_kernel(
    const float* __restrict__ x, const float* __restrict__ gamma,
    const float* __restrict__ beta, OT* __restrict__ out, int rows)
{
    int gw   = (blockIdx.x * blockDim.x + threadIdx.x) >> 5;
    int lane = threadIdx.x & 31;
    if (gw >= rows) return;
    const float* xr = x + (size_t)gw * DIMC;
    float s = 0.f, s2 = 0.f;
    #pragma unroll
    for (int i = lane; i < DIMC; i += 32) { float v = xr[i]; s += v; s2 += v*v; }
    #pragma unroll
    for (int o = 16; o; o >>= 1) {
        s  += __shfl_xor_sync(0xffffffffu, s,  o);
        s2 += __shfl_xor_sync(0xffffffffu, s2, o);
    }
    float mu  = s * (1.f/DIMC);
    float var = s2 * (1.f/DIMC) - mu*mu;
    float inv = rsqrtf(var + 1e-5f);
    OT* orow = out + (size_t)gw * DIMC;
    #pragma unroll
    for (int i = lane; i < DIMC; i += 32)
        orow[i] = (OT)((xr[i] - mu) * inv * gamma[i] + beta[i]);
}

// ---------------- depthwise 3x3 conv, NHWC, pad=1; 4 ch/thread, fp16 in --
__global__ __launch_bounds__(256) void dwconv_kernel(
    const __half* __restrict__ xn, const float* __restrict__ w,
    const float* __restrict__ b, __half* __restrict__ xs)
{
    int idx = blockIdx.x * blockDim.x + threadIdx.x;   // 0 .. TOK*DIMC/4-1
    if (idx >= TOK*(DIMC/4)) return;
    int c4 = idx % (DIMC/4);
    int p  = idx / (DIMC/4);
    int c  = c4 * 4;
    int xq = p % WW;
    int yq = (p / WW) % HH;
    int n  = p / SEQ;

    float4 bb = *(const float4*)(b + c);
    float a0 = bb.x, a1 = bb.y, a2 = bb.z, a3 = bb.w;
    const float* w0 = w + (c+0)*9;
    const float* w1 = w + (c+1)*9;
    const float* w2 = w + (c+2)*9;
    const float* w3 = w + (c+3)*9;

    #pragma unroll
    for (int ky = 0; ky < 3; ky++) {
        int yy = yq + ky - 1;
        if (yy < 0 || yy >= HH) continue;
        #pragma unroll
        for (int kx = 0; kx < 3; kx++) {
            int xx = xq + kx - 1;
            if (xx < 0 || xx >= WW) continue;
            uint2 pk = *(const uint2*)(xn + ((size_t)n*SEQ + yy*WW + xx)*DIMC + c);
            float2 f01 = __half22float2(*(__half2*)&pk.x);
            float2 f23 = __half22float2(*(__half2*)&pk.y);
            int t = ky*3 + kx;
            a0 = fmaf(w0[t], f01.x, a0);
            a1 = fmaf(w1[t], f01.y, a1);
            a2 = fmaf(w2[t], f23.x, a2);
            a3 = fmaf(w3[t], f23.y, a3);
        }
    }
    __half2 h01 = __floats2half2_rn(a0, a1);
    __half2 h23 = __floats2half2_rn(a2, a3);
    uint2 pk;
    pk.x = *(uint32_t*)&h01;
    pk.y = *(uint32_t*)&h23;
    *(uint2*)(xs + (size_t)p*DIMC + c) = pk;
}

// ---------------- all 6 weight transposes [K,N]->fp16 [N,K(stride)] ------
struct TransParams {
    const float* in[6];
    __half*      out[6];
    int K[6], N[6], ostr[6];
};
__global__ __launch_bounds__(256) void transpose_all_kernel(TransParams tp)
{
    int id = blockIdx.z;
    int K = tp.K[id], N = tp.N[id], ostr = tp.ostr[id];
    int kb = blockIdx.x * 32, nb = blockIdx.y * 32;
    if (kb >= K || nb >= N) return;
    const float* in = tp.in[id];
    __half* out = tp.out[id];
    __shared__ float t[32][33];
    int tx = threadIdx.x & 31, ty = threadIdx.x >> 5;   // 32 x 8
    #pragma unroll
    for (int i = 0; i < 32; i += 8)
        t[ty+i][tx] = in[(size_t)(kb+ty+i)*N + nb+tx];
    __syncthreads();
    #pragma unroll
    for (int i = 0; i < 32; i += 8)
        out[(size_t)(nb+ty+i)*ostr + kb+tx] = __float2half(t[tx][ty+i]);
}

// ---------------- fp16 tensor GEMM, K-tile 64, 3-stage, ldmatrix ---------
// C[M,N] = act(A[M,K] @ Bt[N,K]^T + bias) + add.  ACT: 0=none, 1=exact GELU.
// CTA: 128 threads, tile 128 x 128. 4 warps as 2(m) x 2(n); warp tile 64x64.
// Fragments via ldmatrix.x4 (4 A-loads + 4 B-loads per k16 step).
#define STAGES 3
#define APITCH 144                 // 64 halves (128B) + 16B pad
#define ABYTES (128*APITCH)
#define STB    (2*ABYTES)
#define GSMEM  (STAGES*STB)        // 110592

template<int ACT, typename CT>
__global__ __launch_bounds__(128) void tc_gemm(
    const __half* __restrict__ A, const __half* __restrict__ Bt,
    const float* __restrict__ bias, const float* __restrict__ addp,
    CT* __restrict__ C, int M, int N, int K)
{
    extern __shared__ char smem[];
    const uint32_t sbase = smem_to_u32(smem);

    const int tid  = threadIdx.x;
    const int wid  = tid >> 5;
    const int lane = tid & 31;
    const int wm   = wid & 1;                // warp m (2)
    const int wn   = wid >> 1;               // warp n (2)
    const int gid  = lane >> 2;              // 0..7
    const int tig  = lane & 3;               // 0..3
    const int m0   = blockIdx.y * 128;
    const int n0   = blockIdx.x * 128;
    const int nk   = K >> 6;                 // 64-k tiles

    // per-lane ldmatrix row offsets (tile-quad q = lane>>3, row-in-tile = lane&7)
    const int rowin = lane & 7;
    const int q     = lane >> 3;
    const uint32_t off_a = (uint32_t)(((q & 1)*8 + rowin)*APITCH + (q >> 1)*16);
    const uint32_t off_b = (uint32_t)(((q >> 1)*8 + rowin)*APITCH + (q & 1)*16);

    float acc[4][8][4];
    #pragma unroll
    for (int mi = 0; mi < 4; mi++)
        #pragma unroll
        for (int ni = 0; ni < 8; ni++)
            #pragma unroll
            for (int p = 0; p < 4; p++) acc[mi][ni][p] = 0.f;

    // ---- tile loader: global -> smem stage via cp.async (16B = 8 halves) --
    auto load_tile = [&](int i) {
        uint32_t sa = sbase + (i % STAGES) * STB;
        uint32_t sb = sa + ABYTES;
        const __half* Ag = A  + (size_t)m0 * K + i*64;
        const __half* Bg = Bt + (size_t)n0 * K + i*64;
        #pragma unroll
        for (int t = 0; t < 8; t++) {                 // A: 1024 chunks
            int f = tid + t*128;
            int r = f >> 3, kc = f & 7;
            CP_ASYNC16(sa + r*APITCH + kc*16, Ag + (size_t)r*K + kc*8);
        }
        #pragma unroll
        for (int t = 0; t < 8; t++) {                 // B: 1024 chunks
            int f = tid + t*128;
            int r = f >> 3, kc = f & 7;
            CP_ASYNC16(sb + r*APITCH + kc*16, Bg + (size_t)r*K + kc*8);
        }
    };

    load_tile(0); CP_COMMIT();
    load_tile(1); CP_COMMIT();

    uint32_t af[2][4][4];
    uint32_t bf[2][8][2];

    for (int i = 0; i < nk; i++) {
        CP_WAIT(1);
        __syncthreads();
        if (i + 2 < nk) load_tile(i + 2);
        CP_COMMIT();

        uint32_t sa = sbase + (i % STAGES) * STB;
        uint32_t sb = sa + ABYTES;
        const uint32_t abase = sa + (wm*64)*APITCH + off_a;
        const uint32_t bbase = sb + (wn*64)*APITCH + off_b;

        // prefetch ks=0 fragments into buffer 0 (4 + 4 ldmatrix.x4)
        #pragma unroll
        for (int mi = 0; mi < 4; mi++)
            LDSM_X4(af[0][mi][0], af[0][mi][1], af[0][mi][2], af[0][mi][3],
                    abase + mi*16*APITCH);
        #pragma unroll
        for (int j = 0; j < 4; j++)
            LDSM_X4(bf[0][2*j][0], bf[0][2*j][1], bf[0][2*j+1][0], bf[0][2*j+1][1],
                    bbase + j*16*APITCH);

        #pragma unroll
        for (int ks = 0; ks < 4; ks++) {
            int cur = ks & 1, nxt = cur ^ 1;
            if (ks < 3) {
                uint32_t ko = (ks+1)*32;   // 16 halves = 32 bytes per k16 step
                #pragma unroll
                for (int mi = 0; mi < 4; mi++)
                    LDSM_X4(af[nxt][mi][0], af[nxt][mi][1], af[nxt][mi][2], af[nxt][mi][3],
                            abase + mi*16*APITCH + ko);
                #pragma unroll
                for (int j = 0; j < 4; j++)
                    LDSM_X4(bf[nxt][2*j][0], bf[nxt][2*j][1], bf[nxt][2*j+1][0], bf[nxt][2*j+1][1],
                            bbase + j*16*APITCH + ko);
            }
            #pragma unroll
            for (int mi = 0; mi < 4; mi++)
                #pragma unroll
                for (int ni = 0; ni < 8; ni++)
                    MMA_F16(acc[mi][ni],
                            af[cur][mi][0], af[cur][mi][1], af[cur][mi][2], af[cur][mi][3],
                            bf[cur][ni][0], bf[cur][ni][1]);
        }
    }

    // ---- epilogue ---------------------------------------------------------
    #pragma unroll
    for (int mi = 0; mi < 4; mi++) {
        int r0 = m0 + wm*64 + mi*16 + gid;
        #pragma unroll
        for (int ni = 0; ni < 8; ni++) {
            int cn = n0 + wn*64 + ni*8 + tig*2;
            #pragma unroll
            for (int half = 0; half < 2; half++) {
                int r = r0 + half*8;
                float v0 = acc[mi][ni][half*2+0];
                float v1 = acc[mi][ni][half*2+1];
                if (bias) { v0 += bias[cn]; v1 += bias[cn+1]; }
                if (ACT == 1) {
                    v0 = 0.5f * v0 * (1.f + erff(v0 * 0.70710678118654752f));
                    v1 = 0.5f * v1 * (1.f + erff(v1 * 0.70710678118654752f));
                }
                if (addp) {
                    float2 ad = *(const float2*)(addp + (size_t)r*N + cn);
                    v0 += ad.x; v1 += ad.y;
                }
                if (sizeof(CT) == 2) {
                    __half2 hv = __floats2half2_rn(v0, v1);
                    *(__half2*)((__half*)C + (size_t)r*N + cn) = hv;
                } else {
                    float2 ov; ov.x = v0; ov.y = v1;
                    *(float2*)((float*)C + (size_t)r*N + cn) = ov;
                }
            }
        }
    }
}

// ---------------- minGRU scans, LINEAR domain, fp16 hg -------------------
// h_t = sigmoid(-gate)*h_{t-1} + sigmoid(gate)*g(hid)
// with g(x) = x>=0 ? x+0.5 : sigmoid(x)
__global__ __launch_bounds__(256) void scan_kernel(
    const __half* __restrict__ hg, __half* __restrict__ e)
{
    int idx = blockIdx.x * blockDim.x + threadIdx.x;   // 0 .. 2*NB*DIC-1
    int dir = idx / (NB*DIC);
    int r   = idx % (NB*DIC);
    int n   = r / DIC;
    int c   = r % DIC;
    const int coff  = dir * 1536 + c;                  // hid col; gate at +768
    const int eoff  = dir * 768 + c;
    const size_t base  = (size_t)n * SEQ * 3072;
    const size_t ebase = (size_t)n * SEQ * 1536;

    float h = 0.f;
    int t0  = dir ? SEQ-1 : 0;
    int dt  = dir ? -1 : 1;
    for (int s = 0; s < SEQ; s++) {
        int t = t0 + s*dt;
        size_t row = base + (size_t)t * 3072;
        float hid  = __half2float(hg[row + coff]);
        float gate = __half2float(hg[row + coff + 768]);
        float cs = __fdividef(1.f, 1.f + __expf(gate));        // sigmoid(-gate)
        float g  = (hid >= 0.f) ? (hid + 0.5f)
                                : __fdividef(1.f, 1.f + __expf(-hid));
        float v  = (1.f - cs) * g;
        h = fmaf(cs, h, v);
        e[ebase + (size_t)t*1536 + eoff] = __float2half(h);
    }
}

// ---------------- launch -------------------------------------------------
extern "C" void kernel_launch(void* const* d_in, const int* in_sizes, int n_in,
                              void* d_out, int out_size)
{
    const float* x        = (const float*)d_in[0];
    const float* gamma1   = (const float*)d_in[1];
    const float* beta1    = (const float*)d_in[2];
    const float* dwc_w    = (const float*)d_in[3];
    const float* dwc_b    = (const float*)d_in[4];
    const float* gru1_w   = (const float*)d_in[5];
    const float* gru1_out = (const float*)d_in[6];
    const float* gru2_w   = (const float*)d_in[7];
    const float* gru2_out = (const float*)d_in[8];
    const float* gamma2   = (const float*)d_in[9];
    const float* beta2    = (const float*)d_in[10];
    const float* p1_w     = (const float*)d_in[11];
    const float* p1_b     = (const float*)d_in[12];
    const float* p2_w     = (const float*)d_in[13];
    const float* p2_b     = (const float*)d_in[14];
    float* out = (float*)d_out;

    float *y;
    __half *xn, *xs, *hg, *e, *yn, *yh, *wT, *oT, *p1T, *p2T;
    cudaGetSymbolAddress((void**)&xn,  g_xn);
    cudaGetSymbolAddress((void**)&xs,  g_xs);
    cudaGetSymbolAddress((void**)&hg,  g_hg);
    cudaGetSymbolAddress((void**)&e,   g_e);
    cudaGetSymbolAddress((void**)&y,   g_y);
    cudaGetSymbolAddress((void**)&yn,  g_yn);
    cudaGetSymbolAddress((void**)&yh,  g_yh);
    cudaGetSymbolAddress((void**)&wT,  g_wT);
    cudaGetSymbolAddress((void**)&oT,  g_oT);
    cudaGetSymbolAddress((void**)&p1T, g_p1T);
    cudaGetSymbolAddress((void**)&p2T, g_p2T);

    cudaFuncSetAttribute(tc_gemm<0,float>,  cudaFuncAttributeMaxDynamicSharedMemorySize, GSMEM);
    cudaFuncSetAttribute(tc_gemm<0,__half>, cudaFuncAttributeMaxDynamicSharedMemorySize, GSMEM);
    cudaFuncSetAttribute(tc_gemm<1,__half>, cudaFuncAttributeMaxDynamicSharedMemorySize, GSMEM);

    // 0. all weight transposes in one launch (K-major fp16 B operands)
    {
        TransParams tp;
        tp.in[0]=gru1_w;   tp.out[0]=wT;                      tp.K[0]=DIMC; tp.N[0]=2*DIC; tp.ostr[0]=DIMC;
        tp.in[1]=gru2_w;   tp.out[1]=wT+(size_t)1536*DIMC;    tp.K[1]=DIMC; tp.N[1]=2*DIC; tp.ostr[1]=DIMC;
        tp.in[2]=gru1_out; tp.out[2]=oT;                      tp.K[2]=DIC;  tp.N[2]=DIMC;  tp.ostr[2]=1536;
        tp.in[3]=gru2_out; tp.out[3]=oT+768;                  tp.K[3]=DIC;  tp.N[3]=DIMC;  tp.ostr[3]=1536;
        tp.in[4]=p1_w;     tp.out[4]=p1T;                     tp.K[4]=DIMC; tp.N[4]=MLPD;  tp.ostr[4]=DIMC;
        tp.in[5]=p2_w;     tp.out[5]=p2T;                     tp.K[5]=MLPD; tp.N[5]=DIMC;  tp.ostr[5]=MLPD;
        transpose_all_kernel<<<dim3(48, 48, 6), 256>>>(tp);
    }
    // 1. LN1 (fp16 out -> conv input)
    ln_kernel<__half><<<(TOK*32 + 255)/256, 256>>>(x, gamma1, beta1, xn, TOK);
    // 2. depthwise conv 3x3 (fp16 in/out, 4 ch/thread)
    dwconv_kernel<<<(TOK*(DIMC/4) + 255)/256, 256>>>(xn, dwc_w, dwc_b, xs);
    // 3. fused GRU input projections: hg = xs @ [W1|W2]  (N=3072, K=384), fp16 out
    tc_gemm<0,__half><<<dim3(3072/128, TOK/128), 128, GSMEM>>>(
        xs, wT, nullptr, nullptr, hg, TOK, 3072, DIMC);
    // 4. forward + backward minGRU scans (linear domain) -> e[tok][1536] fp16
    scan_kernel<<<(2*NB*DIC)/256, 256>>>(hg, e);
    // 5. fused output projections + residual: y = e @ [O1;O2] + x  (K=1536), f32
    tc_gemm<0,float><<<dim3(DIMC/128, TOK/128), 128, GSMEM>>>(
        e, oT, nullptr, x, y, TOK, DIMC, 1536);
    // 6. LN2 (fp16 out)
    ln_kernel<__half><<<(TOK*32 + 255)/256, 256>>>(y, gamma2, beta2, yn, TOK);
    // 7. MLP up + exact GELU (fp16 out)
    tc_gemm<1,__half><<<dim3(MLPD/128, TOK/128), 128, GSMEM>>>(
        yn, p1T, p1_b, nullptr, yh, TOK, MLPD, DIMC);
    // 8. MLP down + bias + residual -> out (f32)
    tc_gemm<0,float><<<dim3(DIMC/128, TOK/128), 128, GSMEM>>>(
        yh, p2T, p2_b, y, out, TOK, DIMC, MLPD);
}

// round 13
// speedup vs baseline: 6.3214x; 1.0937x over previous
#include <cuda_runtime.h>
#include <cuda_fp16.h>
#include <math.h>
#include <stdint.h>

// ---------------- problem constants (fixed by reference) ----------------
#define NB    32
#define HH    32
#define WW    32
#define SEQ   1024          // H*W
#define DIMC  384
#define DIC   768           // 2*DIM
#define MLPD  1536          // 4*DIM
#define TOK   (NB*SEQ)      // 32768 tokens

// ---------------- scratch (device globals; no runtime alloc) ------------
__device__ __align__(16) __half g_xn [(size_t)TOK*DIMC];
__device__ __align__(16) __half g_xs [(size_t)TOK*DIMC];
__device__ __align__(16) __half g_hg [(size_t)TOK*3072];   // [tok][dir*1536+{hid,gate}]
__device__ __align__(16) __half g_e  [(size_t)TOK*1536];   // [tok][dir*768 + c]
__device__ float g_y  [(size_t)TOK*DIMC];
__device__ __align__(16) __half g_yn [(size_t)TOK*DIMC];
__device__ __align__(16) __half g_yh [(size_t)TOK*MLPD];
// transposed weights (K-major, [N][K]) for the B operand, fp16
__device__ __align__(16) __half g_wT  [(size_t)3072*DIMC];
__device__ __align__(16) __half g_oT  [(size_t)DIMC*1536]; // cols 0-767 o1^T, 768-1535 o2^T
__device__ __align__(16) __half g_p1T [(size_t)MLPD*DIMC];
__device__ __align__(16) __half g_p2T [(size_t)DIMC*MLPD];

// ================= small helpers ========================================
__device__ __forceinline__ uint32_t smem_to_u32(const void* p) {
    uint32_t a;
    asm("{ .reg .u64 t; cvta.to.shared.u64 t, %1; cvt.u32.u64 %0, t; }"
        : "=r"(a) : "l"(p));
    return a;
}
#define CP_ASYNC16(dst, src) \
    asm volatile("cp.async.cg.shared.global [%0], [%1], 16;" \
                 :: "r"(dst), "l"(src) : "memory")
#define CP_COMMIT() asm volatile("cp.async.commit_group;" ::: "memory")
#define CP_WAIT(n)  asm volatile("cp.async.wait_group %0;" :: "n"(n) : "memory")

// ldmatrix x4: four 8x8 b16 tiles; lanes 0-7/8-15/16-23/24-31 address tiles 0-3
#define LDSM_X4(r0,r1,r2,r3, addr)                                          \
    asm volatile("ldmatrix.sync.aligned.m8n8.x4.shared.b16 {%0,%1,%2,%3}, [%4];" \
        : "=r"(r0), "=r"(r1), "=r"(r2), "=r"(r3) : "r"(addr))

#define MMA_F16(d, a0,a1,a2,a3, b0,b1)                                      \
    asm volatile(                                                           \
        "mma.sync.aligned.m16n8k16.row.col.f32.f16.f16.f32 "                \
        "{%0,%1,%2,%3}, {%4,%5,%6,%7}, {%8,%9}, {%0,%1,%2,%3};\n"           \
        : "+f"(d[0]), "+f"(d[1]), "+f"(d[2]), "+f"(d[3])                    \
        : "r"(a0), "r"(a1), "r"(a2), "r"(a3), "r"(b0), "r"(b1))

// ---------------- layer norm: one warp per token row ---------------------
template<typename OT>
__global__ __launch_bounds__(256) void ln_kernel(
    const float* __restrict__ x, const float* __restrict__ gamma,
    const float* __restrict__ beta, OT* __restrict__ out, int rows)
{
    int gw   = (blockIdx.x * blockDim.x + threadIdx.x) >> 5;
    int lane = threadIdx.x & 31;
    if (gw >= rows) return;
    const float* xr = x + (size_t)gw * DIMC;
    float s = 0.f, s2 = 0.f;
    #pragma unroll
    for (int i = lane; i < DIMC; i += 32) { float v = xr[i]; s += v; s2 += v*v; }
    #pragma unroll
    for (int o = 16; o; o >>= 1) {
        s  += __shfl_xor_sync(0xffffffffu, s,  o);
        s2 += __shfl_xor_sync(0xffffffffu, s2, o);
    }
    float mu  = s * (1.f/DIMC);
    float var = s2 * (1.f/DIMC) - mu*mu;
    float inv = rsqrtf(var + 1e-5f);
    OT* orow = out + (size_t)gw * DIMC;
    #pragma unroll
    for (int i = lane; i < DIMC; i += 32)
        orow[i] = (OT)((xr[i] - mu) * inv * gamma[i] + beta[i]);
}

// ---------------- depthwise 3x3 conv, NHWC, pad=1; 4 ch/thread, fp16 in --
__global__ __launch_bounds__(256) void dwconv_kernel(
    const __half* __restrict__ xn, const float* __restrict__ w,
    const float* __restrict__ b, __half* __restrict__ xs)
{
    int idx = blockIdx.x * blockDim.x + threadIdx.x;   // 0 .. TOK*DIMC/4-1
    if (idx >= TOK*(DIMC/4)) return;
    int c4 = idx % (DIMC/4);
    int p  = idx / (DIMC/4);
    int c  = c4 * 4;
    int xq = p % WW;
    int yq = (p / WW) % HH;
    int n  = p / SEQ;

    float4 bb = *(const float4*)(b + c);
    float a0 = bb.x, a1 = bb.y, a2 = bb.z, a3 = bb.w;
    const float* w0 = w + (c+0)*9;
    const float* w1 = w + (c+1)*9;
    const float* w2 = w + (c+2)*9;
    const float* w3 = w + (c+3)*9;

    #pragma unroll
    for (int ky = 0; ky < 3; ky++) {
        int yy = yq + ky - 1;
        if (yy < 0 || yy >= HH) continue;
        #pragma unroll
        for (int kx = 0; kx < 3; kx++) {
            int xx = xq + kx - 1;
            if (xx < 0 || xx >= WW) continue;
            uint2 pk = *(const uint2*)(xn + ((size_t)n*SEQ + yy*WW + xx)*DIMC + c);
            float2 f01 = __half22float2(*(__half2*)&pk.x);
            float2 f23 = __half22float2(*(__half2*)&pk.y);
            int t = ky*3 + kx;
            a0 = fmaf(w0[t], f01.x, a0);
            a1 = fmaf(w1[t], f01.y, a1);
            a2 = fmaf(w2[t], f23.x, a2);
            a3 = fmaf(w3[t], f23.y, a3);
        }
    }
    __half2 h01 = __floats2half2_rn(a0, a1);
    __half2 h23 = __floats2half2_rn(a2, a3);
    uint2 pk;
    pk.x = *(uint32_t*)&h01;
    pk.y = *(uint32_t*)&h23;
    *(uint2*)(xs + (size_t)p*DIMC + c) = pk;
}

// ---------------- all 6 weight transposes [K,N]->fp16 [N,K(stride)] ------
struct TransParams {
    const float* in[6];
    __half*      out[6];
    int K[6], N[6], ostr[6];
};
__global__ __launch_bounds__(256) void transpose_all_kernel(TransParams tp)
{
    int id = blockIdx.z;
    int K = tp.K[id], N = tp.N[id], ostr = tp.ostr[id];
    int kb = blockIdx.x * 32, nb = blockIdx.y * 32;
    if (kb >= K || nb >= N) return;
    const float* in = tp.in[id];
    __half* out = tp.out[id];
    __shared__ float t[32][33];
    int tx = threadIdx.x & 31, ty = threadIdx.x >> 5;   // 32 x 8
    #pragma unroll
    for (int i = 0; i < 32; i += 8)
        t[ty+i][tx] = in[(size_t)(kb+ty+i)*N + nb+tx];
    __syncthreads();
    #pragma unroll
    for (int i = 0; i < 32; i += 8)
        out[(size_t)(nb+ty+i)*ostr + kb+tx] = __float2half(t[tx][ty+i]);
}

// ---------------- fp16 tensor GEMM, occupancy-3, swizzled smem -----------
// C[M,N] = act(A[M,K] @ Bt[N,K]^T + bias) + add.  ACT: 0=none, 1=exact GELU.
// CTA: 128 threads, tile 128(M) x 64(N), K-tile 64. 4 warps as 2(m) x 2(n);
// warp tile 64 x 32. XOR-swizzled smem (no pad) -> 73728 B/CTA -> 3 CTAs/SM.
#define STAGES 3
#define AROWS  128
#define BROWS  64
#define ABYTES (AROWS*128)         // 16384
#define BBYTES (BROWS*128)         // 8192
#define STB    (ABYTES+BBYTES)     // 24576
#define GSMEM  (STAGES*STB)        // 73728

template<int ACT, typename CT>
__global__ __launch_bounds__(128, 3) void tc_gemm(
    const __half* __restrict__ A, const __half* __restrict__ Bt,
    const float* __restrict__ bias, const float* __restrict__ addp,
    CT* __restrict__ C, int M, int N, int K)
{
    extern __shared__ char smem[];
    const uint32_t sbase = smem_to_u32(smem);

    const int tid  = threadIdx.x;
    const int wid  = tid >> 5;
    const int lane = tid & 31;
    const int wm   = wid & 1;                // warp m (2) -> 64 rows
    const int wn   = wid >> 1;               // warp n (2) -> 32 cols
    const int gid  = lane >> 2;              // 0..7
    const int tig  = lane & 3;               // 0..3
    const int m0   = blockIdx.y * 128;
    const int n0   = blockIdx.x * 64;
    const int nk   = K >> 6;                 // 64-k tiles

    // ldmatrix per-lane addressing (tile-quad q = lane>>3, row-in-tile lane&7)
    const int rowin = lane & 7;
    const int q     = lane >> 3;
    const int qa    = q >> 1;                // A k-chunk select
    const int qb    = q & 1;                 // B k-chunk select
    // row*128 offsets (row&7 == rowin for all, since other terms are mult of 8)
    uint32_t aoff[4], boff[2];
    #pragma unroll
    for (int mi = 0; mi < 4; mi++)
        aoff[mi] = (uint32_t)((wm*64 + mi*16 + (q & 1)*8 + rowin) * 128);
    #pragma unroll
    for (int j = 0; j < 2; j++)
        boff[j] = (uint32_t)((wn*32 + j*16 + (q >> 1)*8 + rowin) * 128);

    float acc[4][4][4];
    #pragma unroll
    for (int mi = 0; mi < 4; mi++)
        #pragma unroll
        for (int ni = 0; ni < 4; ni++)
            #pragma unroll
            for (int p = 0; p < 4; p++) acc[mi][ni][p] = 0.f;

    // ---- tile loader: global -> swizzled smem stage (16B chunks) ---------
    auto load_tile = [&](int i) {
        uint32_t sa = sbase + (i % STAGES) * STB;
        uint32_t sb = sa + ABYTES;
        const __half* Ag = A  + (size_t)m0 * K + i*64;
        const __half* Bg = Bt + (size_t)n0 * K + i*64;
        #pragma unroll
        for (int t = 0; t < 8; t++) {                 // A: 1024 chunks
            int f = tid + t*128;
            int r = f >> 3, kc = f & 7;
            CP_ASYNC16(sa + r*128 + ((kc ^ (r & 7)) << 4), Ag + (size_t)r*K + kc*8);
        }
        #pragma unroll
        for (int t = 0; t < 4; t++) {                 // B: 512 chunks
            int f = tid + t*128;
            int r = f >> 3, kc = f & 7;
            CP_ASYNC16(sb + r*128 + ((kc ^ (r & 7)) << 4), Bg + (size_t)r*K + kc*8);
        }
    };

    load_tile(0); CP_COMMIT();
    load_tile(1); CP_COMMIT();

    uint32_t af[2][4][4];
    uint32_t bf[2][4][2];

    for (int i = 0; i < nk; i++) {
        CP_WAIT(1);
        __syncthreads();
        if (i + 2 < nk) load_tile(i + 2);
        CP_COMMIT();

        uint32_t sa = sbase + (i % STAGES) * STB;
        uint32_t sb = sa + ABYTES;

        // prefetch ks=0 fragments into buffer 0 (4 A + 2 B ldmatrix.x4)
        {
            uint32_t ca = (uint32_t)((qa ^ rowin) << 4);
            uint32_t cb = (uint32_t)((qb ^ rowin) << 4);
            #pragma unroll
            for (int mi = 0; mi < 4; mi++)
                LDSM_X4(af[0][mi][0], af[0][mi][1], af[0][mi][2], af[0][mi][3],
                        sa + aoff[mi] + ca);
            #pragma unroll
            for (int j = 0; j < 2; j++)
                LDSM_X4(bf[0][2*j][0], bf[0][2*j][1], bf[0][2*j+1][0], bf[0][2*j+1][1],
                        sb + boff[j] + cb);
        }

        #pragma unroll
        for (int ks = 0; ks < 4; ks++) {
            int cur = ks & 1, nxt = cur ^ 1;
            if (ks < 3) {
                uint32_t ca = (uint32_t)(((2*(ks+1) + qa) ^ rowin) << 4);
                uint32_t cb = (uint32_t)(((2*(ks+1) + qb) ^ rowin) << 4);
                #pragma unroll
                for (int mi = 0; mi < 4; mi++)
                    LDSM_X4(af[nxt][mi][0], af[nxt][mi][1], af[nxt][mi][2], af[nxt][mi][3],
                            sa + aoff[mi] + ca);
                #pragma unroll
                for (int j = 0; j < 2; j++)
                    LDSM_X4(bf[nxt][2*j][0], bf[nxt][2*j][1], bf[nxt][2*j+1][0], bf[nxt][2*j+1][1],
                            sb + boff[j] + cb);
            }
            #pragma unroll
            for (int mi = 0; mi < 4; mi++)
                #pragma unroll
                for (int ni = 0; ni < 4; ni++)
                    MMA_F16(acc[mi][ni],
                            af[cur][mi][0], af[cur][mi][1], af[cur][mi][2], af[cur][mi][3],
                            bf[cur][ni][0], bf[cur][ni][1]);
        }
    }

    // ---- epilogue ---------------------------------------------------------
    #pragma unroll
    for (int mi = 0; mi < 4; mi++) {
        int r0 = m0 + wm*64 + mi*16 + gid;
        #pragma unroll
        for (int ni = 0; ni < 4; ni++) {
            int cn = n0 + wn*32 + ni*8 + tig*2;
            #pragma unroll
            for (int half = 0; half < 2; half++) {
                int r = r0 + half*8;
                float v0 = acc[mi][ni][half*2+0];
                float v1 = acc[mi][ni][half*2+1];
                if (bias) { v0 += bias[cn]; v1 += bias[cn+1]; }
                if (ACT == 1) {
                    v0 = 0.5f * v0 * (1.f + erff(v0 * 0.70710678118654752f));
                    v1 = 0.5f * v1 * (1.f + erff(v1 * 0.70710678118654752f));
                }
                if (addp) {
                    float2 ad = *(const float2*)(addp + (size_t)r*N + cn);
                    v0 += ad.x; v1 += ad.y;
                }
                if (sizeof(CT) == 2) {
                    __half2 hv = __floats2half2_rn(v0, v1);
                    *(__half2*)((__half*)C + (size_t)r*N + cn) = hv;
                } else {
                    float2 ov; ov.x = v0; ov.y = v1;
                    *(float2*)((float*)C + (size_t)r*N + cn) = ov;
                }
            }
        }
    }
}

// ---------------- minGRU scans, LINEAR domain, fp16 hg -------------------
// h_t = sigmoid(-gate)*h_{t-1} + sigmoid(gate)*g(hid)
// with g(x) = x>=0 ? x+0.5 : sigmoid(x)
__global__ __launch_bounds__(256) void scan_kernel(
    const __half* __restrict__ hg, __half* __restrict__ e)
{
    int idx = blockIdx.x * blockDim.x + threadIdx.x;   // 0 .. 2*NB*DIC-1
    int dir = idx / (NB*DIC);
    int r   = idx % (NB*DIC);
    int n   = r / DIC;
    int c   = r % DIC;
    const int coff  = dir * 1536 + c;                  // hid col; gate at +768
    const int eoff  = dir * 768 + c;
    const size_t base  = (size_t)n * SEQ * 3072;
    const size_t ebase = (size_t)n * SEQ * 1536;

    float h = 0.f;
    int t0  = dir ? SEQ-1 : 0;
    int dt  = dir ? -1 : 1;
    for (int s = 0; s < SEQ; s++) {
        int t = t0 + s*dt;
        size_t row = base + (size_t)t * 3072;
        float hid  = __half2float(hg[row + coff]);
        float gate = __half2float(hg[row + coff + 768]);
        float cs = __fdividef(1.f, 1.f + __expf(gate));        // sigmoid(-gate)
        float g  = (hid >= 0.f) ? (hid + 0.5f)
                                : __fdividef(1.f, 1.f + __expf(-hid));
        float v  = (1.f - cs) * g;
        h = fmaf(cs, h, v);
        e[ebase + (size_t)t*1536 + eoff] = __float2half(h);
    }
}

// ---------------- launch -------------------------------------------------
extern "C" void kernel_launch(void* const* d_in, const int* in_sizes, int n_in,
                              void* d_out, int out_size)
{
    const float* x        = (const float*)d_in[0];
    const float* gamma1   = (const float*)d_in[1];
    const float* beta1    = (const float*)d_in[2];
    const float* dwc_w    = (const float*)d_in[3];
    const float* dwc_b    = (const float*)d_in[4];
    const float* gru1_w   = (const float*)d_in[5];
    const float* gru1_out = (const float*)d_in[6];
    const float* gru2_w   = (const float*)d_in[7];
    const float* gru2_out = (const float*)d_in[8];
    const float* gamma2   = (const float*)d_in[9];
    const float* beta2    = (const float*)d_in[10];
    const float* p1_w     = (const float*)d_in[11];
    const float* p1_b     = (const float*)d_in[12];
    const float* p2_w     = (const float*)d_in[13];
    const float* p2_b     = (const float*)d_in[14];
    float* out = (float*)d_out;

    float *y;
    __half *xn, *xs, *hg, *e, *yn, *yh, *wT, *oT, *p1T, *p2T;
    cudaGetSymbolAddress((void**)&xn,  g_xn);
    cudaGetSymbolAddress((void**)&xs,  g_xs);
    cudaGetSymbolAddress((void**)&hg,  g_hg);
    cudaGetSymbolAddress((void**)&e,   g_e);
    cudaGetSymbolAddress((void**)&y,   g_y);
    cudaGetSymbolAddress((void**)&yn,  g_yn);
    cudaGetSymbolAddress((void**)&yh,  g_yh);
    cudaGetSymbolAddress((void**)&wT,  g_wT);
    cudaGetSymbolAddress((void**)&oT,  g_oT);
    cudaGetSymbolAddress((void**)&p1T, g_p1T);
    cudaGetSymbolAddress((void**)&p2T, g_p2T);

    cudaFuncSetAttribute(tc_gemm<0,float>,  cudaFuncAttributeMaxDynamicSharedMemorySize, GSMEM);
    cudaFuncSetAttribute(tc_gemm<0,__half>, cudaFuncAttributeMaxDynamicSharedMemorySize, GSMEM);
    cudaFuncSetAttribute(tc_gemm<1,__half>, cudaFuncAttributeMaxDynamicSharedMemorySize, GSMEM);

    // 0. all weight transposes in one launch (K-major fp16 B operands)
    {
        TransParams tp;
        tp.in[0]=gru1_w;   tp.out[0]=wT;                      tp.K[0]=DIMC; tp.N[0]=2*DIC; tp.ostr[0]=DIMC;
        tp.in[1]=gru2_w;   tp.out[1]=wT+(size_t)1536*DIMC;    tp.K[1]=DIMC; tp.N[1]=2*DIC; tp.ostr[1]=DIMC;
        tp.in[2]=gru1_out; tp.out[2]=oT;                      tp.K[2]=DIC;  tp.N[2]=DIMC;  tp.ostr[2]=1536;
        tp.in[3]=gru2_out; tp.out[3]=oT+768;                  tp.K[3]=DIC;  tp.N[3]=DIMC;  tp.ostr[3]=1536;
        tp.in[4]=p1_w;     tp.out[4]=p1T;                     tp.K[4]=DIMC; tp.N[4]=MLPD;  tp.ostr[4]=DIMC;
        tp.in[5]=p2_w;     tp.out[5]=p2T;                     tp.K[5]=MLPD; tp.N[5]=DIMC;  tp.ostr[5]=MLPD;
        transpose_all_kernel<<<dim3(48, 48, 6), 256>>>(tp);
    }
    // 1. LN1 (fp16 out -> conv input)
    ln_kernel<__half><<<(TOK*32 + 255)/256, 256>>>(x, gamma1, beta1, xn, TOK);
    // 2. depthwise conv 3x3 (fp16 in/out, 4 ch/thread)
    dwconv_kernel<<<(TOK*(DIMC/4) + 255)/256, 256>>>(xn, dwc_w, dwc_b, xs);
    // 3. fused GRU input projections: hg = xs @ [W1|W2]  (N=3072, K=384), fp16 out
    tc_gemm<0,__half><<<dim3(3072/64, TOK/128), 128, GSMEM>>>(
        xs, wT, nullptr, nullptr, hg, TOK, 3072, DIMC);
    // 4. forward + backward minGRU scans (linear domain) -> e[tok][1536] fp16
    scan_kernel<<<(2*NB*DIC)/256, 256>>>(hg, e);
    // 5. fused output projections + residual: y = e @ [O1;O2] + x  (K=1536), f32
    tc_gemm<0,float><<<dim3(DIMC/64, TOK/128), 128, GSMEM>>>(
        e, oT, nullptr, x, y, TOK, DIMC, 1536);
    // 6. LN2 (fp16 out)
    ln_kernel<__half><<<(TOK*32 + 255)/256, 256>>>(y, gamma2, beta2, yn, TOK);
    // 7. MLP up + exact GELU (fp16 out)
    tc_gemm<1,__half><<<dim3(MLPD/64, TOK/128), 128, GSMEM>>>(
        yn, p1T, p1_b, nullptr, yh, TOK, MLPD, DIMC);
    // 8. MLP down + bias + residual -> out (f32)
    tc_gemm<0,float><<<dim3(DIMC/64, TOK/128), 128, GSMEM>>>(
        yh, p2T, p2_b, y, out, TOK, DIMC, MLPD);
}